// round 12
// baseline (speedup 1.0000x reference)
#include <cuda_runtime.h>

#define BATCH 1024

// ---------------- scratch (static device globals: no allocation allowed) ----
__device__ __align__(16) float g_buf1[BATCH * 32 * 20 * 20];   // conv1 out
__device__ __align__(16) float g_buf2[BATCH * 64 * 9 * 9];     // conv2 out
__device__ __align__(16) float g_buf3[BATCH * 64 * 7 * 7];     // conv3 out (flattened h)
__device__ __align__(16) float g_part[7 * BATCH * 256];        // fc1 split-K partials
__device__ __align__(16) float g_h[BATCH * 256];               // fc1 out (relu)
// transposed weights: [ic][ky][kx][oc] so 8 consecutive oc = 2x LDS.128
__device__ __align__(16) float g_w1t[8192];    // [4][8][8][32]
__device__ __align__(16) float g_w2t[32768];   // [32][4][4][64]
__device__ __align__(16) float g_w3t[36864];   // [64][3][3][64]

// ---------------- weight transpose (runs once per launch, ~2us) ------------
__global__ __launch_bounds__(256) void transpose_w_kernel(
    const float* __restrict__ w1, const float* __restrict__ w2,
    const float* __restrict__ w3) {
  int i = blockIdx.x * 256 + threadIdx.x;
  if (i < 8192) {            // [r=ic*ky*kx(256)][oc32] <- [oc][r]
    int oc = i & 31, r = i >> 5;
    g_w1t[i] = w1[oc * 256 + r];
  }
  if (i < 32768) {           // [r(512)][oc64]
    int oc = i & 63, r = i >> 6;
    g_w2t[i] = w2[oc * 512 + r];
  }
  if (i < 36864) {           // [r(576)][oc64]
    int oc = i & 63, r = i >> 6;
    g_w3t[i] = w3[oc * 576 + r];
  }
}

// ---------------- conv1: 4->32, 8x8 stride 4, 84->20, x scaled 1/256 -------
// grid=B, 512 thr. lane 0..127 -> 4 pixels (stride 128), ocg 0..3 -> 8 oc.
// smem: image 28224f + weights(t) 8192f = 145664 B.
__global__ __launch_bounds__(512) void conv1_kernel(
    const float* __restrict__ x, const float* __restrict__ bias) {
  extern __shared__ float sm[];
  float* s_in = sm;
  float* s_w  = sm + 28224;
  float4* s_in4 = (float4*)s_in;
  float4* s_w4  = (float4*)s_w;
  const int n = blockIdx.x;
  const float4* xn = (const float4*)(x + (size_t)n * 28224);
  for (int i = threadIdx.x; i < 7056; i += 512) {
    float4 v = xn[i];
    v.x *= (1.0f / 256.0f); v.y *= (1.0f / 256.0f);
    v.z *= (1.0f / 256.0f); v.w *= (1.0f / 256.0f);
    s_in4[i] = v;
  }
  const float4* wt = (const float4*)g_w1t;
  for (int i = threadIdx.x; i < 2048; i += 512) s_w4[i] = wt[i];
  __syncthreads();

  const int lane = threadIdx.x & 127;
  const int ocg  = threadIdx.x >> 7;   // uniform per warp -> broadcast weight LDS

  float acc[4][8];
  int oy[4], ox[4];
#pragma unroll
  for (int pp = 0; pp < 4; pp++) {
    int p = lane + 128 * pp;
    int pq = (p < 400) ? p : 0;
    oy[pp] = pq / 20;
    ox[pp] = pq - 20 * oy[pp];
#pragma unroll
    for (int j = 0; j < 8; j++) acc[pp][j] = 0.f;
  }

#pragma unroll 1
  for (int ic = 0; ic < 4; ic++) {
#pragma unroll 1
    for (int ky = 0; ky < 8; ky++) {
      int b4[4];
#pragma unroll
      for (int pp = 0; pp < 4; pp++)
        b4[pp] = (ic * 84 + oy[pp] * 4 + ky) * 21 + ox[pp];  // float4 units
#pragma unroll
      for (int half = 0; half < 2; half++) {
        float av[4][4];
#pragma unroll
        for (int pp = 0; pp < 4; pp++) {
          float4 a = s_in4[b4[pp] + half];
          av[pp][0] = a.x; av[pp][1] = a.y; av[pp][2] = a.z; av[pp][3] = a.w;
        }
#pragma unroll
        for (int kx4 = 0; kx4 < 4; kx4++) {
          int widx = (((ic * 8 + ky) * 8 + half * 4 + kx4) * 32 + ocg * 8) >> 2;
          float4 w0 = s_w4[widx], w1 = s_w4[widx + 1];
#pragma unroll
          for (int pp = 0; pp < 4; pp++) {
            float v = av[pp][kx4];
            acc[pp][0] = fmaf(v, w0.x, acc[pp][0]);
            acc[pp][1] = fmaf(v, w0.y, acc[pp][1]);
            acc[pp][2] = fmaf(v, w0.z, acc[pp][2]);
            acc[pp][3] = fmaf(v, w0.w, acc[pp][3]);
            acc[pp][4] = fmaf(v, w1.x, acc[pp][4]);
            acc[pp][5] = fmaf(v, w1.y, acc[pp][5]);
            acc[pp][6] = fmaf(v, w1.z, acc[pp][6]);
            acc[pp][7] = fmaf(v, w1.w, acc[pp][7]);
          }
        }
      }
    }
  }

#pragma unroll
  for (int pp = 0; pp < 4; pp++) {
    int p = lane + 128 * pp;
    if (p < 400) {
#pragma unroll
      for (int j = 0; j < 8; j++) {
        int oc = ocg * 8 + j;
        g_buf1[((size_t)n * 32 + oc) * 400 + p] = fmaxf(acc[pp][j] + bias[oc], 0.f);
      }
    }
  }
}

// ---------------- conv2: 32->64, 4x4 stride 2, 20->9 -----------------------
// grid=B, 512 thr. lane 0..63 -> 2 pixels (stride 64), ocg 0..7 -> 8 oc.
// smem: 12800f + 32768f = 182272 B.
__global__ __launch_bounds__(512) void conv2_kernel(const float* __restrict__ bias) {
  extern __shared__ float sm[];
  float* s_in = sm;           // [32][20][20]
  float* s_w  = sm + 12800;   // transposed [32][4][4][64]
  float4* s_in4 = (float4*)s_in;
  float4* s_w4  = (float4*)s_w;
  const float2* s_in2 = (const float2*)s_in;
  const int n = blockIdx.x;
  const float4* inn = (const float4*)(g_buf1 + (size_t)n * 12800);
  for (int i = threadIdx.x; i < 3200; i += 512) s_in4[i] = inn[i];
  const float4* wt = (const float4*)g_w2t;
  for (int i = threadIdx.x; i < 8192; i += 512) s_w4[i] = wt[i];
  __syncthreads();

  const int lane = threadIdx.x & 63;
  const int ocg  = threadIdx.x >> 6;   // uniform per warp (64-thread groups)

  float acc[2][8];
  int oy[2], ox[2];
#pragma unroll
  for (int pp = 0; pp < 2; pp++) {
    int p = lane + 64 * pp;
    int pq = (p < 81) ? p : 0;
    oy[pp] = pq / 9;
    ox[pp] = pq - 9 * oy[pp];
#pragma unroll
    for (int j = 0; j < 8; j++) acc[pp][j] = 0.f;
  }

#pragma unroll 1
  for (int ic = 0; ic < 32; ic++) {
#pragma unroll 1
    for (int ky = 0; ky < 4; ky++) {
      float av[2][4];
#pragma unroll
      for (int pp = 0; pp < 2; pp++) {
        int b2 = (ic * 20 + oy[pp] * 2 + ky) * 10 + ox[pp];  // float2 units
        float2 a = s_in2[b2], b = s_in2[b2 + 1];
        av[pp][0] = a.x; av[pp][1] = a.y; av[pp][2] = b.x; av[pp][3] = b.y;
      }
#pragma unroll
      for (int kx = 0; kx < 4; kx++) {
        int widx = (((ic * 4 + ky) * 4 + kx) * 64 + ocg * 8) >> 2;
        float4 w0 = s_w4[widx], w1 = s_w4[widx + 1];
#pragma unroll
        for (int pp = 0; pp < 2; pp++) {
          float v = av[pp][kx];
          acc[pp][0] = fmaf(v, w0.x, acc[pp][0]);
          acc[pp][1] = fmaf(v, w0.y, acc[pp][1]);
          acc[pp][2] = fmaf(v, w0.z, acc[pp][2]);
          acc[pp][3] = fmaf(v, w0.w, acc[pp][3]);
          acc[pp][4] = fmaf(v, w1.x, acc[pp][4]);
          acc[pp][5] = fmaf(v, w1.y, acc[pp][5]);
          acc[pp][6] = fmaf(v, w1.z, acc[pp][6]);
          acc[pp][7] = fmaf(v, w1.w, acc[pp][7]);
        }
      }
    }
  }

#pragma unroll
  for (int pp = 0; pp < 2; pp++) {
    int p = lane + 64 * pp;
    if (p < 81) {
#pragma unroll
      for (int j = 0; j < 8; j++) {
        int oc = ocg * 8 + j;
        g_buf2[((size_t)n * 64 + oc) * 81 + p] = fmaxf(acc[pp][j] + bias[oc], 0.f);
      }
    }
  }
}

// ---------------- conv3: 64->64, 3x3 stride 1, 9->7 ------------------------
// grid=B/2, 512 thr: 2 images per CTA (amortize 144KB weight smem, 16 warps).
// Per image: lane 0..31 -> 2 pixels, ocg 0..7 -> 8 oc.
// smem: 2*5184f + 36864f = 188928 B. Writes flattened: buf3[n][oc*49+p].
__global__ __launch_bounds__(512) void conv3_kernel(const float* __restrict__ bias) {
  extern __shared__ float sm[];
  float* s_in = sm;           // [2][64][9][9]
  float* s_w  = sm + 10368;   // transposed [64][3][3][64]
  float4* s_in4 = (float4*)s_in;
  float4* s_w4  = (float4*)s_w;
  const int n0 = blockIdx.x * 2;
  const float4* inn = (const float4*)(g_buf2 + (size_t)n0 * 5184);
  for (int i = threadIdx.x; i < 2592; i += 512) s_in4[i] = inn[i];
  const float4* wt = (const float4*)g_w3t;
  for (int i = threadIdx.x; i < 9216; i += 512) s_w4[i] = wt[i];
  __syncthreads();

  const int img  = threadIdx.x >> 8;         // 0/1
  const int t    = threadIdx.x & 255;
  const int lane = t & 31;
  const int ocg  = t >> 5;                   // uniform per warp
  const float* s_im = s_in + img * 5184;
  const int n = n0 + img;

  float acc[2][8];
  int oy[2], ox[2];
#pragma unroll
  for (int pp = 0; pp < 2; pp++) {
    int p = lane + 32 * pp;
    int pq = (p < 49) ? p : 0;
    oy[pp] = pq / 7;
    ox[pp] = pq - 7 * oy[pp];
#pragma unroll
    for (int j = 0; j < 8; j++) acc[pp][j] = 0.f;
  }

#pragma unroll 1
  for (int ic = 0; ic < 64; ic++) {
#pragma unroll 1
    for (int ky = 0; ky < 3; ky++) {
      float av[2][3];
#pragma unroll
      for (int pp = 0; pp < 2; pp++) {
        int b = (ic * 9 + oy[pp] + ky) * 9 + ox[pp];
        av[pp][0] = s_im[b];
        av[pp][1] = s_im[b + 1];
        av[pp][2] = s_im[b + 2];
      }
#pragma unroll
      for (int kx = 0; kx < 3; kx++) {
        int widx = (((ic * 3 + ky) * 3 + kx) * 64 + ocg * 8) >> 2;
        float4 w0 = s_w4[widx], w1 = s_w4[widx + 1];
#pragma unroll
        for (int pp = 0; pp < 2; pp++) {
          float v = av[pp][kx];
          acc[pp][0] = fmaf(v, w0.x, acc[pp][0]);
          acc[pp][1] = fmaf(v, w0.y, acc[pp][1]);
          acc[pp][2] = fmaf(v, w0.z, acc[pp][2]);
          acc[pp][3] = fmaf(v, w0.w, acc[pp][3]);
          acc[pp][4] = fmaf(v, w1.x, acc[pp][4]);
          acc[pp][5] = fmaf(v, w1.y, acc[pp][5]);
          acc[pp][6] = fmaf(v, w1.z, acc[pp][6]);
          acc[pp][7] = fmaf(v, w1.w, acc[pp][7]);
        }
      }
    }
  }

#pragma unroll
  for (int pp = 0; pp < 2; pp++) {
    int p = lane + 32 * pp;
    if (p < 49) {
#pragma unroll
      for (int j = 0; j < 8; j++) {
        int oc = ocg * 8 + j;
        g_buf3[(size_t)n * 3136 + oc * 49 + p] = fmaxf(acc[pp][j] + bias[oc], 0.f);
      }
    }
  }
}

// ---------------- fc1: [1024,3136] @ [3136,256], split-K=7 SGEMM -----------
// grid (mt=8, nt=4, ks=7), 256 thr. tile 128x64, thread tile 8x4, kc=16.
__global__ __launch_bounds__(256) void fc1_kernel(const float* __restrict__ Bw) {
  __shared__ __align__(16) float sA[128 * 17];
  __shared__ __align__(16) float sB[16 * 64];
  const int mt = blockIdx.x, nt = blockIdx.y, ks = blockIdx.z;
  const int tid = threadIdx.x;
  const int ty = tid >> 4, tx = tid & 15;
  const int m0 = mt * 128, nn0 = nt * 64;
  const float* A = g_buf3;

  float acc[8][4];
#pragma unroll
  for (int i = 0; i < 8; i++)
#pragma unroll
    for (int j = 0; j < 4; j++) acc[i][j] = 0.f;

#pragma unroll 1
  for (int kb = 0; kb < 448; kb += 16) {
    const int k0 = ks * 448 + kb;
#pragma unroll
    for (int li = 0; li < 2; li++) {
      int f = tid + li * 256;          // 0..511
      int m = f >> 2;
      int kk = (f & 3) << 2;
      float4 v = *reinterpret_cast<const float4*>(
          &A[(size_t)(m0 + m) * 3136 + k0 + kk]);
      sA[m * 17 + kk + 0] = v.x;
      sA[m * 17 + kk + 1] = v.y;
      sA[m * 17 + kk + 2] = v.z;
      sA[m * 17 + kk + 3] = v.w;
    }
    {
      int k = tid >> 4;
      int nn4 = (tid & 15) << 2;
      *reinterpret_cast<float4*>(&sB[k * 64 + nn4]) =
          *reinterpret_cast<const float4*>(&Bw[(size_t)(k0 + k) * 256 + nn0 + nn4]);
    }
    __syncthreads();
#pragma unroll
    for (int k = 0; k < 16; k++) {
      float4 b4 = *reinterpret_cast<const float4*>(&sB[k * 64 + tx * 4]);
      float a[8];
#pragma unroll
      for (int i = 0; i < 8; i++) a[i] = sA[(ty * 8 + i) * 17 + k];
#pragma unroll
      for (int i = 0; i < 8; i++) {
        acc[i][0] = fmaf(a[i], b4.x, acc[i][0]);
        acc[i][1] = fmaf(a[i], b4.y, acc[i][1]);
        acc[i][2] = fmaf(a[i], b4.z, acc[i][2]);
        acc[i][3] = fmaf(a[i], b4.w, acc[i][3]);
      }
    }
    __syncthreads();
  }

  float* pout = g_part + (size_t)ks * (BATCH * 256);
#pragma unroll
  for (int i = 0; i < 8; i++)
#pragma unroll
    for (int j = 0; j < 4; j++)
      pout[(size_t)(m0 + ty * 8 + i) * 256 + nn0 + tx * 4 + j] = acc[i][j];
}

// sum the 7 split-K partials + bias + relu
__global__ __launch_bounds__(256) void fc1_reduce_kernel(const float* __restrict__ fb1) {
  int idx = blockIdx.x * 256 + threadIdx.x;  // < 262144
  float s = fb1[idx & 255];
#pragma unroll
  for (int ks = 0; ks < 7; ks++) s += g_part[(size_t)ks * (BATCH * 256) + idx];
  g_h[idx] = fmaxf(s, 0.f);
}

// ---------------- fc2 + softmax + dist broadcast + expected value ----------
__global__ __launch_bounds__(64) void fc2_kernel(
    const float* __restrict__ w2, const float* __restrict__ b2,
    const float* __restrict__ z, int NO, float* __restrict__ out) {
  __shared__ float sh[256];
  __shared__ float red[64];
  const int n = blockIdx.x, t = threadIdx.x;
  for (int i = t; i < 256; i += 64) sh[i] = g_h[n * 256 + i];
  __syncthreads();

  float logit = -3.0e38f;
  if (t < 51) {
    float s = b2[t];
#pragma unroll 4
    for (int k = 0; k < 256; k++) s = fmaf(sh[k], __ldg(&w2[k * 51 + t]), s);
    logit = s;
  }

  red[t] = logit;
  __syncthreads();
#pragma unroll
  for (int off = 32; off > 0; off >>= 1) {
    if (t < off) red[t] = fmaxf(red[t], red[t + off]);
    __syncthreads();
  }
  float mx = red[0];
  __syncthreads();

  float e = (t < 51) ? __expf(logit - mx) : 0.f;
  red[t] = e;
  __syncthreads();
#pragma unroll
  for (int off = 32; off > 0; off >>= 1) {
    if (t < off) red[t] += red[t + off];
    __syncthreads();
  }
  float inv = 1.0f / red[0];
  __syncthreads();
  float p = e * inv;

  red[t] = (t < 51) ? p * z[t] : 0.f;
  __syncthreads();
#pragma unroll
  for (int off = 32; off > 0; off >>= 1) {
    if (t < off) red[t] += red[t + off];
    __syncthreads();
  }
  float resv = red[0];

  if (t < 51) {
    size_t dbase = (size_t)n * NO * 51 + t;
    for (int j = 0; j < NO; j++) out[dbase + (size_t)j * 51] = p;
  }
  if (t == 0) {
    float* ro = out + (size_t)gridDim.x * NO * 51;
    for (int j = 0; j < NO; j++) ro[(size_t)n * NO + j] = resv;
  }
}

// ---------------- launch ----------------------------------------------------
extern "C" void kernel_launch(void* const* d_in, const int* in_sizes, int n_in,
                              void* d_out, int out_size) {
  const float* x   = (const float*)d_in[0];
  const float* cw1 = (const float*)d_in[1];
  const float* cb1 = (const float*)d_in[2];
  const float* cw2 = (const float*)d_in[3];
  const float* cb2 = (const float*)d_in[4];
  const float* cw3 = (const float*)d_in[5];
  const float* cb3 = (const float*)d_in[6];
  const float* fw1 = (const float*)d_in[7];
  const float* fb1 = (const float*)d_in[8];
  const float* fw2 = (const float*)d_in[9];
  const float* fb2 = (const float*)d_in[10];
  const float* z   = (const float*)d_in[11];
  float* out = (float*)d_out;

  int NO = out_size / (BATCH * 52);
  if (NO < 1) NO = 6;

  const int sm1 = (28224 + 8192) * 4;
  const int sm2 = (12800 + 32768) * 4;
  const int sm3 = (10368 + 36864) * 4;
  cudaFuncSetAttribute(conv1_kernel, cudaFuncAttributeMaxDynamicSharedMemorySize, sm1);
  cudaFuncSetAttribute(conv2_kernel, cudaFuncAttributeMaxDynamicSharedMemorySize, sm2);
  cudaFuncSetAttribute(conv3_kernel, cudaFuncAttributeMaxDynamicSharedMemorySize, sm3);

  transpose_w_kernel<<<144, 256>>>(cw1, cw2, cw3);
  conv1_kernel<<<BATCH, 512, sm1>>>(x, cb1);
  conv2_kernel<<<BATCH, 512, sm2>>>(cb2);
  conv3_kernel<<<BATCH / 2, 512, sm3>>>(cb3);
  fc1_kernel<<<dim3(8, 4, 7), 256>>>(fw1);
  fc1_reduce_kernel<<<1024, 256>>>(fb1);
  fc2_kernel<<<BATCH, 64>>>(fw2, fb2, z, NO, out);
}

// round 13
// speedup vs baseline: 1.0514x; 1.0514x over previous
#include <cuda_runtime.h>

#define BATCH 1024

// ---------------- scratch (static device globals: no allocation allowed) ----
__device__ __align__(16) float g_buf1[BATCH * 32 * 20 * 20];   // conv1 out
__device__ __align__(16) float g_buf2[BATCH * 64 * 9 * 9];     // conv2 out
__device__ __align__(16) float g_buf3[BATCH * 64 * 7 * 7];     // conv3 out (flattened h)
__device__ __align__(16) float g_part[7 * BATCH * 256];        // fc1 split-K partials
__device__ __align__(16) float g_h[BATCH * 256];               // fc1 out (relu)
// transposed weights: [ic][ky][kx][oc] so 8 consecutive oc = 2x LDS.128
__device__ __align__(16) float g_w1t[8192];    // [4][8][8][32]
__device__ __align__(16) float g_w2t[32768];   // [32][4][4][64]
__device__ __align__(16) float g_w3t[36864];   // [64][3][3][64]

// ---------------- weight transpose (runs once per launch, ~2us) ------------
__global__ __launch_bounds__(256) void transpose_w_kernel(
    const float* __restrict__ w1, const float* __restrict__ w2,
    const float* __restrict__ w3) {
  int i = blockIdx.x * 256 + threadIdx.x;
  if (i < 8192) {            // [r=ic*ky*kx(256)][oc32] <- [oc][r]
    int oc = i & 31, r = i >> 5;
    g_w1t[i] = w1[oc * 256 + r];
  }
  if (i < 32768) {           // [r(512)][oc64]
    int oc = i & 63, r = i >> 6;
    g_w2t[i] = w2[oc * 512 + r];
  }
  if (i < 36864) {           // [r(576)][oc64]
    int oc = i & 63, r = i >> 6;
    g_w3t[i] = w3[oc * 576 + r];
  }
}

// ---------------- conv1: 4->32, 8x8 stride 4, 84->20, x scaled 1/256 -------
// grid=B, 384 thr (12 warps). lane 0..95 -> 5 pixels (stride 96), ocg 0..3.
// smem: image 28224f + weights(t) 8192f = 145664 B.
__global__ __launch_bounds__(384) void conv1_kernel(
    const float* __restrict__ x, const float* __restrict__ bias) {
  extern __shared__ float sm[];
  float* s_in = sm;
  float* s_w  = sm + 28224;
  float4* s_in4 = (float4*)s_in;
  float4* s_w4  = (float4*)s_w;
  const int n = blockIdx.x;
  const float4* xn = (const float4*)(x + (size_t)n * 28224);
  for (int i = threadIdx.x; i < 7056; i += 384) {
    float4 v = xn[i];
    v.x *= (1.0f / 256.0f); v.y *= (1.0f / 256.0f);
    v.z *= (1.0f / 256.0f); v.w *= (1.0f / 256.0f);
    s_in4[i] = v;
  }
  const float4* wt = (const float4*)g_w1t;
  for (int i = threadIdx.x; i < 2048; i += 384) s_w4[i] = wt[i];
  __syncthreads();

  const int lane = threadIdx.x % 96;
  const int ocg  = threadIdx.x / 96;   // 96 = 3 warps -> uniform per warp

  float acc[5][8];
  int oy[5], ox[5];
#pragma unroll
  for (int pp = 0; pp < 5; pp++) {
    int p = lane + 96 * pp;
    int pq = (p < 400) ? p : 0;
    oy[pp] = pq / 20;
    ox[pp] = pq - 20 * oy[pp];
#pragma unroll
    for (int j = 0; j < 8; j++) acc[pp][j] = 0.f;
  }

#pragma unroll 1
  for (int ic = 0; ic < 4; ic++) {
#pragma unroll 1
    for (int ky = 0; ky < 8; ky++) {
      int b4[5];
#pragma unroll
      for (int pp = 0; pp < 5; pp++)
        b4[pp] = (ic * 84 + oy[pp] * 4 + ky) * 21 + ox[pp];  // float4 units
#pragma unroll
      for (int half = 0; half < 2; half++) {
        float av[5][4];
#pragma unroll
        for (int pp = 0; pp < 5; pp++) {
          float4 a = s_in4[b4[pp] + half];
          av[pp][0] = a.x; av[pp][1] = a.y; av[pp][2] = a.z; av[pp][3] = a.w;
        }
#pragma unroll
        for (int kx4 = 0; kx4 < 4; kx4++) {
          int widx = (((ic * 8 + ky) * 8 + half * 4 + kx4) * 32 + ocg * 8) >> 2;
          float4 w0 = s_w4[widx], w1 = s_w4[widx + 1];
#pragma unroll
          for (int pp = 0; pp < 5; pp++) {
            float v = av[pp][kx4];
            acc[pp][0] = fmaf(v, w0.x, acc[pp][0]);
            acc[pp][1] = fmaf(v, w0.y, acc[pp][1]);
            acc[pp][2] = fmaf(v, w0.z, acc[pp][2]);
            acc[pp][3] = fmaf(v, w0.w, acc[pp][3]);
            acc[pp][4] = fmaf(v, w1.x, acc[pp][4]);
            acc[pp][5] = fmaf(v, w1.y, acc[pp][5]);
            acc[pp][6] = fmaf(v, w1.z, acc[pp][6]);
            acc[pp][7] = fmaf(v, w1.w, acc[pp][7]);
          }
        }
      }
    }
  }

#pragma unroll
  for (int pp = 0; pp < 5; pp++) {
    int p = lane + 96 * pp;
    if (p < 400) {
#pragma unroll
      for (int j = 0; j < 8; j++) {
        int oc = ocg * 8 + j;
        g_buf1[((size_t)n * 32 + oc) * 400 + p] = fmaxf(acc[pp][j] + bias[oc], 0.f);
      }
    }
  }
}

// ---------------- conv2: 32->64, 4x4 stride 2, 20->9 -----------------------
// grid=B, 256 thr (R11 config: best measured). lane 0..31 -> 3 px, ocg 0..7.
// smem: 12800f + 32768f = 182272 B.
__global__ __launch_bounds__(256) void conv2_kernel(const float* __restrict__ bias) {
  extern __shared__ float sm[];
  float* s_in = sm;           // [32][20][20]
  float* s_w  = sm + 12800;   // transposed [32][4][4][64]
  float4* s_in4 = (float4*)s_in;
  float4* s_w4  = (float4*)s_w;
  const float2* s_in2 = (const float2*)s_in;
  const int n = blockIdx.x;
  const float4* inn = (const float4*)(g_buf1 + (size_t)n * 12800);
  for (int i = threadIdx.x; i < 3200; i += 256) s_in4[i] = inn[i];
  const float4* wt = (const float4*)g_w2t;
  for (int i = threadIdx.x; i < 8192; i += 256) s_w4[i] = wt[i];
  __syncthreads();

  const int lane = threadIdx.x & 31;
  const int ocg  = threadIdx.x >> 5;

  float acc[3][8];
  int oy[3], ox[3];
#pragma unroll
  for (int pp = 0; pp < 3; pp++) {
    int p = lane + 32 * pp;
    int pq = (p < 81) ? p : 0;
    oy[pp] = pq / 9;
    ox[pp] = pq - 9 * oy[pp];
#pragma unroll
    for (int j = 0; j < 8; j++) acc[pp][j] = 0.f;
  }

#pragma unroll 1
  for (int ic = 0; ic < 32; ic++) {
#pragma unroll 1
    for (int ky = 0; ky < 4; ky++) {
      float av[3][4];
#pragma unroll
      for (int pp = 0; pp < 3; pp++) {
        int b2 = (ic * 20 + oy[pp] * 2 + ky) * 10 + ox[pp];  // float2 units
        float2 a = s_in2[b2], b = s_in2[b2 + 1];
        av[pp][0] = a.x; av[pp][1] = a.y; av[pp][2] = b.x; av[pp][3] = b.y;
      }
#pragma unroll
      for (int kx = 0; kx < 4; kx++) {
        int widx = (((ic * 4 + ky) * 4 + kx) * 64 + ocg * 8) >> 2;
        float4 w0 = s_w4[widx], w1 = s_w4[widx + 1];
#pragma unroll
        for (int pp = 0; pp < 3; pp++) {
          float v = av[pp][kx];
          acc[pp][0] = fmaf(v, w0.x, acc[pp][0]);
          acc[pp][1] = fmaf(v, w0.y, acc[pp][1]);
          acc[pp][2] = fmaf(v, w0.z, acc[pp][2]);
          acc[pp][3] = fmaf(v, w0.w, acc[pp][3]);
          acc[pp][4] = fmaf(v, w1.x, acc[pp][4]);
          acc[pp][5] = fmaf(v, w1.y, acc[pp][5]);
          acc[pp][6] = fmaf(v, w1.z, acc[pp][6]);
          acc[pp][7] = fmaf(v, w1.w, acc[pp][7]);
        }
      }
    }
  }

#pragma unroll
  for (int pp = 0; pp < 3; pp++) {
    int p = lane + 32 * pp;
    if (p < 81) {
#pragma unroll
      for (int j = 0; j < 8; j++) {
        int oc = ocg * 8 + j;
        g_buf2[((size_t)n * 64 + oc) * 81 + p] = fmaxf(acc[pp][j] + bias[oc], 0.f);
      }
    }
  }
}

// ---------------- conv3: 64->64, 3x3 stride 1, 9->7 ------------------------
// grid=ceil(B/3), 768 thr (24 warps): 3 images per CTA, per-image layout
// unchanged (lane 0..31 -> 2 px, ocg 0..7 -> 8 oc).
// smem: 3*5184f + 36864f = 209664 B. Writes flattened: buf3[n][oc*49+p].
__global__ __launch_bounds__(768) void conv3_kernel(const float* __restrict__ bias) {
  extern __shared__ float sm[];
  float* s_in = sm;           // [3][64][9][9]
  float* s_w  = sm + 15552;   // transposed [64][3][3][64]
  float4* s_in4 = (float4*)s_in;
  float4* s_w4  = (float4*)s_w;
  const int n0 = blockIdx.x * 3;
  int nimg = BATCH - n0; if (nimg > 3) nimg = 3;
  const float4* inn = (const float4*)(g_buf2 + (size_t)n0 * 5184);
  for (int i = threadIdx.x; i < nimg * 1296; i += 768) s_in4[i] = inn[i];
  const float4* wt = (const float4*)g_w3t;
  for (int i = threadIdx.x; i < 9216; i += 768) s_w4[i] = wt[i];
  __syncthreads();

  const int img  = threadIdx.x >> 8;         // 0..2 (256 = 8 warps -> uniform)
  const int t    = threadIdx.x & 255;
  const int lane = t & 31;
  const int ocg  = t >> 5;                   // uniform per warp
  const float* s_im = s_in + img * 5184;
  const int n = n0 + img;

  float acc[2][8];
  int oy[2], ox[2];
#pragma unroll
  for (int pp = 0; pp < 2; pp++) {
    int p = lane + 32 * pp;
    int pq = (p < 49) ? p : 0;
    oy[pp] = pq / 7;
    ox[pp] = pq - 7 * oy[pp];
#pragma unroll
    for (int j = 0; j < 8; j++) acc[pp][j] = 0.f;
  }

#pragma unroll 1
  for (int ic = 0; ic < 64; ic++) {
#pragma unroll 1
    for (int ky = 0; ky < 3; ky++) {
      float av[2][3];
#pragma unroll
      for (int pp = 0; pp < 2; pp++) {
        int b = (ic * 9 + oy[pp] + ky) * 9 + ox[pp];
        av[pp][0] = s_im[b];
        av[pp][1] = s_im[b + 1];
        av[pp][2] = s_im[b + 2];
      }
#pragma unroll
      for (int kx = 0; kx < 3; kx++) {
        int widx = (((ic * 3 + ky) * 3 + kx) * 64 + ocg * 8) >> 2;
        float4 w0 = s_w4[widx], w1 = s_w4[widx + 1];
#pragma unroll
        for (int pp = 0; pp < 2; pp++) {
          float v = av[pp][kx];
          acc[pp][0] = fmaf(v, w0.x, acc[pp][0]);
          acc[pp][1] = fmaf(v, w0.y, acc[pp][1]);
          acc[pp][2] = fmaf(v, w0.z, acc[pp][2]);
          acc[pp][3] = fmaf(v, w0.w, acc[pp][3]);
          acc[pp][4] = fmaf(v, w1.x, acc[pp][4]);
          acc[pp][5] = fmaf(v, w1.y, acc[pp][5]);
          acc[pp][6] = fmaf(v, w1.z, acc[pp][6]);
          acc[pp][7] = fmaf(v, w1.w, acc[pp][7]);
        }
      }
    }
  }

  if (n < BATCH) {
#pragma unroll
    for (int pp = 0; pp < 2; pp++) {
      int p = lane + 32 * pp;
      if (p < 49) {
#pragma unroll
        for (int j = 0; j < 8; j++) {
          int oc = ocg * 8 + j;
          g_buf3[(size_t)n * 3136 + oc * 49 + p] = fmaxf(acc[pp][j] + bias[oc], 0.f);
        }
      }
    }
  }
}

// ---------------- fc1: [1024,3136] @ [3136,256], split-K=7 SGEMM -----------
// grid (mt=8, nt=4, ks=7), 256 thr. tile 128x64, thread tile 8x4, kc=16.
__global__ __launch_bounds__(256) void fc1_kernel(const float* __restrict__ Bw) {
  __shared__ __align__(16) float sA[128 * 17];
  __shared__ __align__(16) float sB[16 * 64];
  const int mt = blockIdx.x, nt = blockIdx.y, ks = blockIdx.z;
  const int tid = threadIdx.x;
  const int ty = tid >> 4, tx = tid & 15;
  const int m0 = mt * 128, nn0 = nt * 64;
  const float* A = g_buf3;

  float acc[8][4];
#pragma unroll
  for (int i = 0; i < 8; i++)
#pragma unroll
    for (int j = 0; j < 4; j++) acc[i][j] = 0.f;

#pragma unroll 1
  for (int kb = 0; kb < 448; kb += 16) {
    const int k0 = ks * 448 + kb;
#pragma unroll
    for (int li = 0; li < 2; li++) {
      int f = tid + li * 256;          // 0..511
      int m = f >> 2;
      int kk = (f & 3) << 2;
      float4 v = *reinterpret_cast<const float4*>(
          &A[(size_t)(m0 + m) * 3136 + k0 + kk]);
      sA[m * 17 + kk + 0] = v.x;
      sA[m * 17 + kk + 1] = v.y;
      sA[m * 17 + kk + 2] = v.z;
      sA[m * 17 + kk + 3] = v.w;
    }
    {
      int k = tid >> 4;
      int nn4 = (tid & 15) << 2;
      *reinterpret_cast<float4*>(&sB[k * 64 + nn4]) =
          *reinterpret_cast<const float4*>(&Bw[(size_t)(k0 + k) * 256 + nn0 + nn4]);
    }
    __syncthreads();
#pragma unroll
    for (int k = 0; k < 16; k++) {
      float4 b4 = *reinterpret_cast<const float4*>(&sB[k * 64 + tx * 4]);
      float a[8];
#pragma unroll
      for (int i = 0; i < 8; i++) a[i] = sA[(ty * 8 + i) * 17 + k];
#pragma unroll
      for (int i = 0; i < 8; i++) {
        acc[i][0] = fmaf(a[i], b4.x, acc[i][0]);
        acc[i][1] = fmaf(a[i], b4.y, acc[i][1]);
        acc[i][2] = fmaf(a[i], b4.z, acc[i][2]);
        acc[i][3] = fmaf(a[i], b4.w, acc[i][3]);
      }
    }
    __syncthreads();
  }

  float* pout = g_part + (size_t)ks * (BATCH * 256);
#pragma unroll
  for (int i = 0; i < 8; i++)
#pragma unroll
    for (int j = 0; j < 4; j++)
      pout[(size_t)(m0 + ty * 8 + i) * 256 + nn0 + tx * 4 + j] = acc[i][j];
}

// sum the 7 split-K partials + bias + relu
__global__ __launch_bounds__(256) void fc1_reduce_kernel(const float* __restrict__ fb1) {
  int idx = blockIdx.x * 256 + threadIdx.x;  // < 262144
  float s = fb1[idx & 255];
#pragma unroll
  for (int ks = 0; ks < 7; ks++) s += g_part[(size_t)ks * (BATCH * 256) + idx];
  g_h[idx] = fmaxf(s, 0.f);
}

// ---------------- fc2 + softmax + dist broadcast + expected value ----------
__global__ __launch_bounds__(64) void fc2_kernel(
    const float* __restrict__ w2, const float* __restrict__ b2,
    const float* __restrict__ z, int NO, float* __restrict__ out) {
  __shared__ float sh[256];
  __shared__ float red[64];
  const int n = blockIdx.x, t = threadIdx.x;
  for (int i = t; i < 256; i += 64) sh[i] = g_h[n * 256 + i];
  __syncthreads();

  float logit = -3.0e38f;
  if (t < 51) {
    float s = b2[t];
#pragma unroll 4
    for (int k = 0; k < 256; k++) s = fmaf(sh[k], __ldg(&w2[k * 51 + t]), s);
    logit = s;
  }

  red[t] = logit;
  __syncthreads();
#pragma unroll
  for (int off = 32; off > 0; off >>= 1) {
    if (t < off) red[t] = fmaxf(red[t], red[t + off]);
    __syncthreads();
  }
  float mx = red[0];
  __syncthreads();

  float e = (t < 51) ? __expf(logit - mx) : 0.f;
  red[t] = e;
  __syncthreads();
#pragma unroll
  for (int off = 32; off > 0; off >>= 1) {
    if (t < off) red[t] += red[t + off];
    __syncthreads();
  }
  float inv = 1.0f / red[0];
  __syncthreads();
  float p = e * inv;

  red[t] = (t < 51) ? p * z[t] : 0.f;
  __syncthreads();
#pragma unroll
  for (int off = 32; off > 0; off >>= 1) {
    if (t < off) red[t] += red[t + off];
    __syncthreads();
  }
  float resv = red[0];

  if (t < 51) {
    size_t dbase = (size_t)n * NO * 51 + t;
    for (int j = 0; j < NO; j++) out[dbase + (size_t)j * 51] = p;
  }
  if (t == 0) {
    float* ro = out + (size_t)gridDim.x * NO * 51;
    for (int j = 0; j < NO; j++) ro[(size_t)n * NO + j] = resv;
  }
}

// ---------------- launch ----------------------------------------------------
extern "C" void kernel_launch(void* const* d_in, const int* in_sizes, int n_in,
                              void* d_out, int out_size) {
  const float* x   = (const float*)d_in[0];
  const float* cw1 = (const float*)d_in[1];
  const float* cb1 = (const float*)d_in[2];
  const float* cw2 = (const float*)d_in[3];
  const float* cb2 = (const float*)d_in[4];
  const float* cw3 = (const float*)d_in[5];
  const float* cb3 = (const float*)d_in[6];
  const float* fw1 = (const float*)d_in[7];
  const float* fb1 = (const float*)d_in[8];
  const float* fw2 = (const float*)d_in[9];
  const float* fb2 = (const float*)d_in[10];
  const float* z   = (const float*)d_in[11];
  float* out = (float*)d_out;

  int NO = out_size / (BATCH * 52);
  if (NO < 1) NO = 6;

  const int sm1 = (28224 + 8192) * 4;
  const int sm2 = (12800 + 32768) * 4;
  const int sm3 = (15552 + 36864) * 4;
  cudaFuncSetAttribute(conv1_kernel, cudaFuncAttributeMaxDynamicSharedMemorySize, sm1);
  cudaFuncSetAttribute(conv2_kernel, cudaFuncAttributeMaxDynamicSharedMemorySize, sm2);
  cudaFuncSetAttribute(conv3_kernel, cudaFuncAttributeMaxDynamicSharedMemorySize, sm3);

  transpose_w_kernel<<<144, 256>>>(cw1, cw2, cw3);
  conv1_kernel<<<BATCH, 384, sm1>>>(x, cb1);
  conv2_kernel<<<BATCH, 256, sm2>>>(cb2);
  conv3_kernel<<<(BATCH + 2) / 3, 768, sm3>>>(cb3);
  fc1_kernel<<<dim3(8, 4, 7), 256>>>(fw1);
  fc1_reduce_kernel<<<1024, 256>>>(fb1);
  fc2_kernel<<<BATCH, 64>>>(fw2, fb2, z, NO, out);
}

// round 14
// speedup vs baseline: 1.0935x; 1.0400x over previous
#include <cuda_runtime.h>

#define BATCH 1024

// ---------------- scratch (static device globals: no allocation allowed) ----
__device__ __align__(16) float g_buf1[BATCH * 32 * 20 * 20];   // conv1 out
__device__ __align__(16) float g_buf2[BATCH * 64 * 9 * 9];     // conv2 out
__device__ __align__(16) float g_buf3[BATCH * 64 * 7 * 7];     // conv3 out (flattened h)
__device__ __align__(16) float g_part[7 * BATCH * 256];        // fc1 split-K partials
__device__ __align__(16) float g_h[BATCH * 256];               // fc1 out (relu)
// transposed weights: [ic][ky][kx][oc] so 8 consecutive oc = 2x LDS.128
__device__ __align__(16) float g_w1t[8192];    // [4][8][8][32]
__device__ __align__(16) float g_w2t[32768];   // [32][4][4][64]
__device__ __align__(16) float g_w3t[36864];   // [64][3][3][64]

// ---------------- weight transpose (runs once per launch, ~2us) ------------
__global__ __launch_bounds__(256) void transpose_w_kernel(
    const float* __restrict__ w1, const float* __restrict__ w2,
    const float* __restrict__ w3) {
  int i = blockIdx.x * 256 + threadIdx.x;
  if (i < 8192) {            // [r=ic*ky*kx(256)][oc32] <- [oc][r]
    int oc = i & 31, r = i >> 5;
    g_w1t[i] = w1[oc * 256 + r];
  }
  if (i < 32768) {           // [r(512)][oc64]
    int oc = i & 63, r = i >> 6;
    g_w2t[i] = w2[oc * 512 + r];
  }
  if (i < 36864) {           // [r(576)][oc64]
    int oc = i & 63, r = i >> 6;
    g_w3t[i] = w3[oc * 576 + r];
  }
}

// ---------------- conv1: 4->32, 8x8 stride 4, 84->20, x scaled 1/256 -------
// grid=B, 384 thr (12 warps). lane 0..95 -> 5 pixels (stride 96), ocg 0..3.
// smem: image 28224f + weights(t) 8192f = 145664 B.
__global__ __launch_bounds__(384) void conv1_kernel(
    const float* __restrict__ x, const float* __restrict__ bias) {
  extern __shared__ float sm[];
  float* s_in = sm;
  float* s_w  = sm + 28224;
  float4* s_in4 = (float4*)s_in;
  float4* s_w4  = (float4*)s_w;
  const int n = blockIdx.x;
  const float4* xn = (const float4*)(x + (size_t)n * 28224);
  for (int i = threadIdx.x; i < 7056; i += 384) {
    float4 v = xn[i];
    v.x *= (1.0f / 256.0f); v.y *= (1.0f / 256.0f);
    v.z *= (1.0f / 256.0f); v.w *= (1.0f / 256.0f);
    s_in4[i] = v;
  }
  const float4* wt = (const float4*)g_w1t;
  for (int i = threadIdx.x; i < 2048; i += 384) s_w4[i] = wt[i];
  __syncthreads();

  const int lane = threadIdx.x % 96;
  const int ocg  = threadIdx.x / 96;   // 96 = 3 warps -> uniform per warp

  float acc[5][8];
  int oy[5], ox[5];
#pragma unroll
  for (int pp = 0; pp < 5; pp++) {
    int p = lane + 96 * pp;
    int pq = (p < 400) ? p : 0;
    oy[pp] = pq / 20;
    ox[pp] = pq - 20 * oy[pp];
#pragma unroll
    for (int j = 0; j < 8; j++) acc[pp][j] = 0.f;
  }

#pragma unroll 1
  for (int ic = 0; ic < 4; ic++) {
#pragma unroll 1
    for (int ky = 0; ky < 8; ky++) {
      int b4[5];
#pragma unroll
      for (int pp = 0; pp < 5; pp++)
        b4[pp] = (ic * 84 + oy[pp] * 4 + ky) * 21 + ox[pp];  // float4 units
#pragma unroll
      for (int half = 0; half < 2; half++) {
        float av[5][4];
#pragma unroll
        for (int pp = 0; pp < 5; pp++) {
          float4 a = s_in4[b4[pp] + half];
          av[pp][0] = a.x; av[pp][1] = a.y; av[pp][2] = a.z; av[pp][3] = a.w;
        }
#pragma unroll
        for (int kx4 = 0; kx4 < 4; kx4++) {
          int widx = (((ic * 8 + ky) * 8 + half * 4 + kx4) * 32 + ocg * 8) >> 2;
          float4 w0 = s_w4[widx], w1 = s_w4[widx + 1];
#pragma unroll
          for (int pp = 0; pp < 5; pp++) {
            float v = av[pp][kx4];
            acc[pp][0] = fmaf(v, w0.x, acc[pp][0]);
            acc[pp][1] = fmaf(v, w0.y, acc[pp][1]);
            acc[pp][2] = fmaf(v, w0.z, acc[pp][2]);
            acc[pp][3] = fmaf(v, w0.w, acc[pp][3]);
            acc[pp][4] = fmaf(v, w1.x, acc[pp][4]);
            acc[pp][5] = fmaf(v, w1.y, acc[pp][5]);
            acc[pp][6] = fmaf(v, w1.z, acc[pp][6]);
            acc[pp][7] = fmaf(v, w1.w, acc[pp][7]);
          }
        }
      }
    }
  }

#pragma unroll
  for (int pp = 0; pp < 5; pp++) {
    int p = lane + 96 * pp;
    if (p < 400) {
#pragma unroll
      for (int j = 0; j < 8; j++) {
        int oc = ocg * 8 + j;
        g_buf1[((size_t)n * 32 + oc) * 400 + p] = fmaxf(acc[pp][j] + bias[oc], 0.f);
      }
    }
  }
}

// ---------------- conv2: 32->64, 4x4 stride 2, 20->9 -----------------------
// grid=B, 256 thr (best measured). lane 0..31 -> 3 px, ocg 0..7.
// smem: 12800f + 32768f = 182272 B.
__global__ __launch_bounds__(256) void conv2_kernel(const float* __restrict__ bias) {
  extern __shared__ float sm[];
  float* s_in = sm;           // [32][20][20]
  float* s_w  = sm + 12800;   // transposed [32][4][4][64]
  float4* s_in4 = (float4*)s_in;
  float4* s_w4  = (float4*)s_w;
  const float2* s_in2 = (const float2*)s_in;
  const int n = blockIdx.x;
  const float4* inn = (const float4*)(g_buf1 + (size_t)n * 12800);
  for (int i = threadIdx.x; i < 3200; i += 256) s_in4[i] = inn[i];
  const float4* wt = (const float4*)g_w2t;
  for (int i = threadIdx.x; i < 8192; i += 256) s_w4[i] = wt[i];
  __syncthreads();

  const int lane = threadIdx.x & 31;
  const int ocg  = threadIdx.x >> 5;

  float acc[3][8];
  int oy[3], ox[3];
#pragma unroll
  for (int pp = 0; pp < 3; pp++) {
    int p = lane + 32 * pp;
    int pq = (p < 81) ? p : 0;
    oy[pp] = pq / 9;
    ox[pp] = pq - 9 * oy[pp];
#pragma unroll
    for (int j = 0; j < 8; j++) acc[pp][j] = 0.f;
  }

#pragma unroll 1
  for (int ic = 0; ic < 32; ic++) {
#pragma unroll 1
    for (int ky = 0; ky < 4; ky++) {
      float av[3][4];
#pragma unroll
      for (int pp = 0; pp < 3; pp++) {
        int b2 = (ic * 20 + oy[pp] * 2 + ky) * 10 + ox[pp];  // float2 units
        float2 a = s_in2[b2], b = s_in2[b2 + 1];
        av[pp][0] = a.x; av[pp][1] = a.y; av[pp][2] = b.x; av[pp][3] = b.y;
      }
#pragma unroll
      for (int kx = 0; kx < 4; kx++) {
        int widx = (((ic * 4 + ky) * 4 + kx) * 64 + ocg * 8) >> 2;
        float4 w0 = s_w4[widx], w1 = s_w4[widx + 1];
#pragma unroll
        for (int pp = 0; pp < 3; pp++) {
          float v = av[pp][kx];
          acc[pp][0] = fmaf(v, w0.x, acc[pp][0]);
          acc[pp][1] = fmaf(v, w0.y, acc[pp][1]);
          acc[pp][2] = fmaf(v, w0.z, acc[pp][2]);
          acc[pp][3] = fmaf(v, w0.w, acc[pp][3]);
          acc[pp][4] = fmaf(v, w1.x, acc[pp][4]);
          acc[pp][5] = fmaf(v, w1.y, acc[pp][5]);
          acc[pp][6] = fmaf(v, w1.z, acc[pp][6]);
          acc[pp][7] = fmaf(v, w1.w, acc[pp][7]);
        }
      }
    }
  }

#pragma unroll
  for (int pp = 0; pp < 3; pp++) {
    int p = lane + 32 * pp;
    if (p < 81) {
#pragma unroll
      for (int j = 0; j < 8; j++) {
        int oc = ocg * 8 + j;
        g_buf2[((size_t)n * 64 + oc) * 81 + p] = fmaxf(acc[pp][j] + bias[oc], 0.f);
      }
    }
  }
}

// ---------------- conv3: 64->64, 3x3 stride 1, 9->7 ------------------------
// ROW-REUSE version: thread = full output row (7 px) x 8 oc. Per (ic,ky):
// 9 input LDS + 6 broadcast weight LDS.128 feed 168 FFMA (ratio 11.2:1).
// grid=B/4, 256 thr. warp = ocg (uniform weights), lane = img*7+row over
// 4 images (28/32 lanes). Image stride padded to 5192 (mod 32 = 8) so all
// 28 lane addresses hit distinct banks.
// smem: 4*5192f + 36864f = 230528 B (< 232448 cap).
#define C3_STRIDE 5192
__global__ __launch_bounds__(256) void conv3_kernel(const float* __restrict__ bias) {
  extern __shared__ float sm[];
  float* s_in = sm;                       // [4][5192]
  float* s_w  = sm + 4 * C3_STRIDE;       // transposed [64][3][3][64]
  float4* s_w4 = (float4*)s_w;
  const int n0 = blockIdx.x * 4;
#pragma unroll
  for (int img = 0; img < 4; img++) {
    const float4* src = (const float4*)(g_buf2 + (size_t)(n0 + img) * 5184);
    float4* dst = (float4*)(s_in + img * C3_STRIDE);
    for (int i = threadIdx.x; i < 1296; i += 256) dst[i] = src[i];
  }
  const float4* wt = (const float4*)g_w3t;
  for (int i = threadIdx.x; i < 9216; i += 256) s_w4[i] = wt[i];
  __syncthreads();

  const int ocg  = threadIdx.x >> 5;       // warp id -> 8 oc (uniform per warp)
  const int lane = threadIdx.x & 31;
  const int img  = lane / 7;               // 0..3 valid; lanes 28..31 idle
  const int row  = lane % 7;
  const bool active = (lane < 28);
  const float* s_im = s_in + (active ? img : 0) * C3_STRIDE;

  float acc[7][8];
#pragma unroll
  for (int p = 0; p < 7; p++)
#pragma unroll
    for (int j = 0; j < 8; j++) acc[p][j] = 0.f;

#pragma unroll 1
  for (int ic = 0; ic < 64; ic++) {
#pragma unroll 1
    for (int ky = 0; ky < 3; ky++) {
      const float* ip = s_im + (ic * 9 + row + ky) * 9;
      float in[9];
#pragma unroll
      for (int i = 0; i < 9; i++) in[i] = ip[i];
#pragma unroll
      for (int kx = 0; kx < 3; kx++) {
        int widx = (((ic * 3 + ky) * 3 + kx) * 64 + ocg * 8) >> 2;
        float4 w0 = s_w4[widx], w1 = s_w4[widx + 1];
#pragma unroll
        for (int p = 0; p < 7; p++) {
          float v = in[p + kx];
          acc[p][0] = fmaf(v, w0.x, acc[p][0]);
          acc[p][1] = fmaf(v, w0.y, acc[p][1]);
          acc[p][2] = fmaf(v, w0.z, acc[p][2]);
          acc[p][3] = fmaf(v, w0.w, acc[p][3]);
          acc[p][4] = fmaf(v, w1.x, acc[p][4]);
          acc[p][5] = fmaf(v, w1.y, acc[p][5]);
          acc[p][6] = fmaf(v, w1.z, acc[p][6]);
          acc[p][7] = fmaf(v, w1.w, acc[p][7]);
        }
      }
    }
  }

  if (active) {
    const int n = n0 + img;
#pragma unroll
    for (int j = 0; j < 8; j++) {
      int oc = ocg * 8 + j;
      float b = bias[oc];
      float* dst = g_buf3 + (size_t)n * 3136 + oc * 49 + row * 7;
#pragma unroll
      for (int p = 0; p < 7; p++) dst[p] = fmaxf(acc[p][j] + b, 0.f);
    }
  }
}

// ---------------- fc1: [1024,3136] @ [3136,256], split-K=7 SGEMM -----------
// grid (mt=8, nt=4, ks=7), 256 thr. tile 128x64, thread tile 8x4, kc=16.
__global__ __launch_bounds__(256) void fc1_kernel(const float* __restrict__ Bw) {
  __shared__ __align__(16) float sA[128 * 17];
  __shared__ __align__(16) float sB[16 * 64];
  const int mt = blockIdx.x, nt = blockIdx.y, ks = blockIdx.z;
  const int tid = threadIdx.x;
  const int ty = tid >> 4, tx = tid & 15;
  const int m0 = mt * 128, nn0 = nt * 64;
  const float* A = g_buf3;

  float acc[8][4];
#pragma unroll
  for (int i = 0; i < 8; i++)
#pragma unroll
    for (int j = 0; j < 4; j++) acc[i][j] = 0.f;

#pragma unroll 1
  for (int kb = 0; kb < 448; kb += 16) {
    const int k0 = ks * 448 + kb;
#pragma unroll
    for (int li = 0; li < 2; li++) {
      int f = tid + li * 256;          // 0..511
      int m = f >> 2;
      int kk = (f & 3) << 2;
      float4 v = *reinterpret_cast<const float4*>(
          &A[(size_t)(m0 + m) * 3136 + k0 + kk]);
      sA[m * 17 + kk + 0] = v.x;
      sA[m * 17 + kk + 1] = v.y;
      sA[m * 17 + kk + 2] = v.z;
      sA[m * 17 + kk + 3] = v.w;
    }
    {
      int k = tid >> 4;
      int nn4 = (tid & 15) << 2;
      *reinterpret_cast<float4*>(&sB[k * 64 + nn4]) =
          *reinterpret_cast<const float4*>(&Bw[(size_t)(k0 + k) * 256 + nn0 + nn4]);
    }
    __syncthreads();
#pragma unroll
    for (int k = 0; k < 16; k++) {
      float4 b4 = *reinterpret_cast<const float4*>(&sB[k * 64 + tx * 4]);
      float a[8];
#pragma unroll
      for (int i = 0; i < 8; i++) a[i] = sA[(ty * 8 + i) * 17 + k];
#pragma unroll
      for (int i = 0; i < 8; i++) {
        acc[i][0] = fmaf(a[i], b4.x, acc[i][0]);
        acc[i][1] = fmaf(a[i], b4.y, acc[i][1]);
        acc[i][2] = fmaf(a[i], b4.z, acc[i][2]);
        acc[i][3] = fmaf(a[i], b4.w, acc[i][3]);
      }
    }
    __syncthreads();
  }

  float* pout = g_part + (size_t)ks * (BATCH * 256);
#pragma unroll
  for (int i = 0; i < 8; i++)
#pragma unroll
    for (int j = 0; j < 4; j++)
      pout[(size_t)(m0 + ty * 8 + i) * 256 + nn0 + tx * 4 + j] = acc[i][j];
}

// sum the 7 split-K partials + bias + relu
__global__ __launch_bounds__(256) void fc1_reduce_kernel(const float* __restrict__ fb1) {
  int idx = blockIdx.x * 256 + threadIdx.x;  // < 262144
  float s = fb1[idx & 255];
#pragma unroll
  for (int ks = 0; ks < 7; ks++) s += g_part[(size_t)ks * (BATCH * 256) + idx];
  g_h[idx] = fmaxf(s, 0.f);
}

// ---------------- fc2 + softmax + dist broadcast + expected value ----------
__global__ __launch_bounds__(64) void fc2_kernel(
    const float* __restrict__ w2, const float* __restrict__ b2,
    const float* __restrict__ z, int NO, float* __restrict__ out) {
  __shared__ float sh[256];
  __shared__ float red[64];
  const int n = blockIdx.x, t = threadIdx.x;
  for (int i = t; i < 256; i += 64) sh[i] = g_h[n * 256 + i];
  __syncthreads();

  float logit = -3.0e38f;
  if (t < 51) {
    float s = b2[t];
#pragma unroll 4
    for (int k = 0; k < 256; k++) s = fmaf(sh[k], __ldg(&w2[k * 51 + t]), s);
    logit = s;
  }

  red[t] = logit;
  __syncthreads();
#pragma unroll
  for (int off = 32; off > 0; off >>= 1) {
    if (t < off) red[t] = fmaxf(red[t], red[t + off]);
    __syncthreads();
  }
  float mx = red[0];
  __syncthreads();

  float e = (t < 51) ? __expf(logit - mx) : 0.f;
  red[t] = e;
  __syncthreads();
#pragma unroll
  for (int off = 32; off > 0; off >>= 1) {
    if (t < off) red[t] += red[t + off];
    __syncthreads();
  }
  float inv = 1.0f / red[0];
  __syncthreads();
  float p = e * inv;

  red[t] = (t < 51) ? p * z[t] : 0.f;
  __syncthreads();
#pragma unroll
  for (int off = 32; off > 0; off >>= 1) {
    if (t < off) red[t] += red[t + off];
    __syncthreads();
  }
  float resv = red[0];

  if (t < 51) {
    size_t dbase = (size_t)n * NO * 51 + t;
    for (int j = 0; j < NO; j++) out[dbase + (size_t)j * 51] = p;
  }
  if (t == 0) {
    float* ro = out + (size_t)gridDim.x * NO * 51;
    for (int j = 0; j < NO; j++) ro[(size_t)n * NO + j] = resv;
  }
}

// ---------------- launch ----------------------------------------------------
extern "C" void kernel_launch(void* const* d_in, const int* in_sizes, int n_in,
                              void* d_out, int out_size) {
  const float* x   = (const float*)d_in[0];
  const float* cw1 = (const float*)d_in[1];
  const float* cb1 = (const float*)d_in[2];
  const float* cw2 = (const float*)d_in[3];
  const float* cb2 = (const float*)d_in[4];
  const float* cw3 = (const float*)d_in[5];
  const float* cb3 = (const float*)d_in[6];
  const float* fw1 = (const float*)d_in[7];
  const float* fb1 = (const float*)d_in[8];
  const float* fw2 = (const float*)d_in[9];
  const float* fb2 = (const float*)d_in[10];
  const float* z   = (const float*)d_in[11];
  float* out = (float*)d_out;

  int NO = out_size / (BATCH * 52);
  if (NO < 1) NO = 6;

  const int sm1 = (28224 + 8192) * 4;
  const int sm2 = (12800 + 32768) * 4;
  const int sm3 = (4 * C3_STRIDE + 36864) * 4;   // 230528 B
  cudaFuncSetAttribute(conv1_kernel, cudaFuncAttributeMaxDynamicSharedMemorySize, sm1);
  cudaFuncSetAttribute(conv2_kernel, cudaFuncAttributeMaxDynamicSharedMemorySize, sm2);
  cudaFuncSetAttribute(conv3_kernel, cudaFuncAttributeMaxDynamicSharedMemorySize, sm3);

  transpose_w_kernel<<<144, 256>>>(cw1, cw2, cw3);
  conv1_kernel<<<BATCH, 384, sm1>>>(x, cb1);
  conv2_kernel<<<BATCH, 256, sm2>>>(cb2);
  conv3_kernel<<<BATCH / 4, 256, sm3>>>(cb3);
  fc1_kernel<<<dim3(8, 4, 7), 256>>>(fw1);
  fc1_reduce_kernel<<<1024, 256>>>(fb1);
  fc2_kernel<<<BATCH, 64>>>(fw2, fb2, z, NO, out);
}

// round 15
// speedup vs baseline: 1.1730x; 1.0727x over previous
#include <cuda_runtime.h>

#define BATCH 1024

// ---------------- scratch (static device globals: no allocation allowed) ----
__device__ __align__(16) float g_buf1[BATCH * 32 * 20 * 20];   // conv1 out
__device__ __align__(16) float g_buf2[BATCH * 64 * 9 * 9];     // conv2 out
__device__ __align__(16) float g_buf3[BATCH * 64 * 7 * 7];     // conv3 out (flattened h)
__device__ __align__(16) float g_part[7 * BATCH * 256];        // fc1 split-K partials
__device__ __align__(16) float g_h[BATCH * 256];               // fc1 out (relu)
// transposed weights: [ic][ky][kx][oc] so consecutive oc = broadcast LDS.128
__device__ __align__(16) float g_w1t[8192];    // [4][8][8][32]
__device__ __align__(16) float g_w2t[32768];   // [32][4][4][64]
__device__ __align__(16) float g_w3t[36864];   // [64][3][3][64]

// ---------------- weight transpose (runs once per launch, ~2us) ------------
__global__ __launch_bounds__(256) void transpose_w_kernel(
    const float* __restrict__ w1, const float* __restrict__ w2,
    const float* __restrict__ w3) {
  int i = blockIdx.x * 256 + threadIdx.x;
  if (i < 8192) {            // [r=ic*ky*kx(256)][oc32] <- [oc][r]
    int oc = i & 31, r = i >> 5;
    g_w1t[i] = w1[oc * 256 + r];
  }
  if (i < 32768) {           // [r(512)][oc64]
    int oc = i & 63, r = i >> 6;
    g_w2t[i] = w2[oc * 512 + r];
  }
  if (i < 36864) {           // [r(576)][oc64]
    int oc = i & 63, r = i >> 6;
    g_w3t[i] = w3[oc * 576 + r];
  }
}

// ---------------- conv1: 4->32, 8x8 stride 4, 84->20, x scaled 1/256 -------
// R11 config (measured best): grid=B, 256 thr. lane 0..63 -> 7 px (stride 64),
// ocg 0..3 -> 8 oc. smem: 28224f + 8192f = 145664 B.
__global__ __launch_bounds__(256) void conv1_kernel(
    const float* __restrict__ x, const float* __restrict__ bias) {
  extern __shared__ float sm[];
  float* s_in = sm;
  float* s_w  = sm + 28224;
  float4* s_in4 = (float4*)s_in;
  float4* s_w4  = (float4*)s_w;
  const int n = blockIdx.x;
  const float4* xn = (const float4*)(x + (size_t)n * 28224);
  for (int i = threadIdx.x; i < 7056; i += 256) {
    float4 v = xn[i];
    v.x *= (1.0f / 256.0f); v.y *= (1.0f / 256.0f);
    v.z *= (1.0f / 256.0f); v.w *= (1.0f / 256.0f);
    s_in4[i] = v;
  }
  const float4* wt = (const float4*)g_w1t;
  for (int i = threadIdx.x; i < 2048; i += 256) s_w4[i] = wt[i];
  __syncthreads();

  const int lane = threadIdx.x & 63;
  const int ocg  = threadIdx.x >> 6;   // uniform per warp -> broadcast weight LDS

  float acc[7][8];
  int oy[7], ox[7];
#pragma unroll
  for (int pp = 0; pp < 7; pp++) {
    int p = lane + 64 * pp;
    int pq = (p < 400) ? p : 0;
    oy[pp] = pq / 20;
    ox[pp] = pq - 20 * oy[pp];
#pragma unroll
    for (int j = 0; j < 8; j++) acc[pp][j] = 0.f;
  }

#pragma unroll 1
  for (int ic = 0; ic < 4; ic++) {
#pragma unroll 1
    for (int ky = 0; ky < 8; ky++) {
      int b4[7];
#pragma unroll
      for (int pp = 0; pp < 7; pp++)
        b4[pp] = (ic * 84 + oy[pp] * 4 + ky) * 21 + ox[pp];  // float4 units
#pragma unroll
      for (int half = 0; half < 2; half++) {
        float av[7][4];
#pragma unroll
        for (int pp = 0; pp < 7; pp++) {
          float4 a = s_in4[b4[pp] + half];
          av[pp][0] = a.x; av[pp][1] = a.y; av[pp][2] = a.z; av[pp][3] = a.w;
        }
#pragma unroll
        for (int kx4 = 0; kx4 < 4; kx4++) {
          int widx = (((ic * 8 + ky) * 8 + half * 4 + kx4) * 32 + ocg * 8) >> 2;
          float4 w0 = s_w4[widx], w1 = s_w4[widx + 1];
#pragma unroll
          for (int pp = 0; pp < 7; pp++) {
            float v = av[pp][kx4];
            acc[pp][0] = fmaf(v, w0.x, acc[pp][0]);
            acc[pp][1] = fmaf(v, w0.y, acc[pp][1]);
            acc[pp][2] = fmaf(v, w0.z, acc[pp][2]);
            acc[pp][3] = fmaf(v, w0.w, acc[pp][3]);
            acc[pp][4] = fmaf(v, w1.x, acc[pp][4]);
            acc[pp][5] = fmaf(v, w1.y, acc[pp][5]);
            acc[pp][6] = fmaf(v, w1.z, acc[pp][6]);
            acc[pp][7] = fmaf(v, w1.w, acc[pp][7]);
          }
        }
      }
    }
  }

#pragma unroll
  for (int pp = 0; pp < 7; pp++) {
    int p = lane + 64 * pp;
    if (p < 400) {
#pragma unroll
      for (int j = 0; j < 8; j++) {
        int oc = ocg * 8 + j;
        g_buf1[((size_t)n * 32 + oc) * 400 + p] = fmaxf(acc[pp][j] + bias[oc], 0.f);
      }
    }
  }
}

// ---------------- conv2: 32->64, 4x4 stride 2, 20->9 -----------------------
// grid=B, 256 thr (best measured). lane 0..31 -> 3 px, ocg 0..7.
// smem: 12800f + 32768f = 182272 B.
__global__ __launch_bounds__(256) void conv2_kernel(const float* __restrict__ bias) {
  extern __shared__ float sm[];
  float* s_in = sm;           // [32][20][20]
  float* s_w  = sm + 12800;   // transposed [32][4][4][64]
  float4* s_in4 = (float4*)s_in;
  float4* s_w4  = (float4*)s_w;
  const float2* s_in2 = (const float2*)s_in;
  const int n = blockIdx.x;
  const float4* inn = (const float4*)(g_buf1 + (size_t)n * 12800);
  for (int i = threadIdx.x; i < 3200; i += 256) s_in4[i] = inn[i];
  const float4* wt = (const float4*)g_w2t;
  for (int i = threadIdx.x; i < 8192; i += 256) s_w4[i] = wt[i];
  __syncthreads();

  const int lane = threadIdx.x & 31;
  const int ocg  = threadIdx.x >> 5;

  float acc[3][8];
  int oy[3], ox[3];
#pragma unroll
  for (int pp = 0; pp < 3; pp++) {
    int p = lane + 32 * pp;
    int pq = (p < 81) ? p : 0;
    oy[pp] = pq / 9;
    ox[pp] = pq - 9 * oy[pp];
#pragma unroll
    for (int j = 0; j < 8; j++) acc[pp][j] = 0.f;
  }

#pragma unroll 1
  for (int ic = 0; ic < 32; ic++) {
#pragma unroll 1
    for (int ky = 0; ky < 4; ky++) {
      float av[3][4];
#pragma unroll
      for (int pp = 0; pp < 3; pp++) {
        int b2 = (ic * 20 + oy[pp] * 2 + ky) * 10 + ox[pp];  // float2 units
        float2 a = s_in2[b2], b = s_in2[b2 + 1];
        av[pp][0] = a.x; av[pp][1] = a.y; av[pp][2] = b.x; av[pp][3] = b.y;
      }
#pragma unroll
      for (int kx = 0; kx < 4; kx++) {
        int widx = (((ic * 4 + ky) * 4 + kx) * 64 + ocg * 8) >> 2;
        float4 w0 = s_w4[widx], w1 = s_w4[widx + 1];
#pragma unroll
        for (int pp = 0; pp < 3; pp++) {
          float v = av[pp][kx];
          acc[pp][0] = fmaf(v, w0.x, acc[pp][0]);
          acc[pp][1] = fmaf(v, w0.y, acc[pp][1]);
          acc[pp][2] = fmaf(v, w0.z, acc[pp][2]);
          acc[pp][3] = fmaf(v, w0.w, acc[pp][3]);
          acc[pp][4] = fmaf(v, w1.x, acc[pp][4]);
          acc[pp][5] = fmaf(v, w1.y, acc[pp][5]);
          acc[pp][6] = fmaf(v, w1.z, acc[pp][6]);
          acc[pp][7] = fmaf(v, w1.w, acc[pp][7]);
        }
      }
    }
  }

#pragma unroll
  for (int pp = 0; pp < 3; pp++) {
    int p = lane + 32 * pp;
    if (p < 81) {
#pragma unroll
      for (int j = 0; j < 8; j++) {
        int oc = ocg * 8 + j;
        g_buf2[((size_t)n * 64 + oc) * 81 + p] = fmaxf(acc[pp][j] + bias[oc], 0.f);
      }
    }
  }
}

// ---------------- conv3: 64->64, 3x3 stride 1, 9->7 ------------------------
// ROW-REUSE + 16 warps: thread = full 7-px output row x 4 oc.
// Per (ic,ky): 9 input LDS + 3 broadcast weight LDS.128 -> 84 FFMA (7:1),
// with 512 thr = 16 warps/SM for latency hiding.
// warp = ocg 0..15 (4 oc each, uniform weights), lane = img*7+row over
// 4 images (28/32 lanes). Image stride 5192 (mod 32 = 8): 28 lanes hit
// distinct banks. smem: 4*5192f + 36864f = 230528 B.
#define C3_STRIDE 5192
__global__ __launch_bounds__(512) void conv3_kernel(const float* __restrict__ bias) {
  extern __shared__ float sm[];
  float* s_in = sm;                       // [4][5192]
  float* s_w  = sm + 4 * C3_STRIDE;       // transposed [64][3][3][64]
  float4* s_w4 = (float4*)s_w;
  const int n0 = blockIdx.x * 4;
#pragma unroll
  for (int img = 0; img < 4; img++) {
    const float4* src = (const float4*)(g_buf2 + (size_t)(n0 + img) * 5184);
    float4* dst = (float4*)(s_in + img * C3_STRIDE);
    for (int i = threadIdx.x; i < 1296; i += 512) dst[i] = src[i];
  }
  const float4* wt = (const float4*)g_w3t;
  for (int i = threadIdx.x; i < 9216; i += 512) s_w4[i] = wt[i];
  __syncthreads();

  const int ocg  = threadIdx.x >> 5;       // warp id 0..15 -> 4 oc (uniform)
  const int lane = threadIdx.x & 31;
  const int img  = lane / 7;               // 0..3 valid; lanes 28..31 idle
  const int row  = lane % 7;
  const bool active = (lane < 28);
  const float* s_im = s_in + (active ? img : 0) * C3_STRIDE;

  float acc[7][4];
#pragma unroll
  for (int p = 0; p < 7; p++)
#pragma unroll
    for (int j = 0; j < 4; j++) acc[p][j] = 0.f;

#pragma unroll 1
  for (int ic = 0; ic < 64; ic++) {
#pragma unroll 1
    for (int ky = 0; ky < 3; ky++) {
      const float* ip = s_im + (ic * 9 + row + ky) * 9;
      float in[9];
#pragma unroll
      for (int i = 0; i < 9; i++) in[i] = ip[i];
#pragma unroll
      for (int kx = 0; kx < 3; kx++) {
        // one LDS.128: 4 oc for this warp
        int widx = (((ic * 3 + ky) * 3 + kx) * 64 + ocg * 4) >> 2;
        float4 w0 = s_w4[widx];
#pragma unroll
        for (int p = 0; p < 7; p++) {
          float v = in[p + kx];
          acc[p][0] = fmaf(v, w0.x, acc[p][0]);
          acc[p][1] = fmaf(v, w0.y, acc[p][1]);
          acc[p][2] = fmaf(v, w0.z, acc[p][2]);
          acc[p][3] = fmaf(v, w0.w, acc[p][3]);
        }
      }
    }
  }

  if (active) {
    const int n = n0 + img;
#pragma unroll
    for (int j = 0; j < 4; j++) {
      int oc = ocg * 4 + j;
      float b = bias[oc];
      float* dst = g_buf3 + (size_t)n * 3136 + oc * 49 + row * 7;
#pragma unroll
      for (int p = 0; p < 7; p++) dst[p] = fmaxf(acc[p][j] + b, 0.f);
    }
  }
}

// ---------------- fc1: [1024,3136] @ [3136,256], split-K=7 SGEMM -----------
// grid (mt=8, nt=4, ks=7), 256 thr. tile 128x64, thread tile 8x4, kc=16.
__global__ __launch_bounds__(256) void fc1_kernel(const float* __restrict__ Bw) {
  __shared__ __align__(16) float sA[128 * 17];
  __shared__ __align__(16) float sB[16 * 64];
  const int mt = blockIdx.x, nt = blockIdx.y, ks = blockIdx.z;
  const int tid = threadIdx.x;
  const int ty = tid >> 4, tx = tid & 15;
  const int m0 = mt * 128, nn0 = nt * 64;
  const float* A = g_buf3;

  float acc[8][4];
#pragma unroll
  for (int i = 0; i < 8; i++)
#pragma unroll
    for (int j = 0; j < 4; j++) acc[i][j] = 0.f;

#pragma unroll 1
  for (int kb = 0; kb < 448; kb += 16) {
    const int k0 = ks * 448 + kb;
#pragma unroll
    for (int li = 0; li < 2; li++) {
      int f = tid + li * 256;          // 0..511
      int m = f >> 2;
      int kk = (f & 3) << 2;
      float4 v = *reinterpret_cast<const float4*>(
          &A[(size_t)(m0 + m) * 3136 + k0 + kk]);
      sA[m * 17 + kk + 0] = v.x;
      sA[m * 17 + kk + 1] = v.y;
      sA[m * 17 + kk + 2] = v.z;
      sA[m * 17 + kk + 3] = v.w;
    }
    {
      int k = tid >> 4;
      int nn4 = (tid & 15) << 2;
      *reinterpret_cast<float4*>(&sB[k * 64 + nn4]) =
          *reinterpret_cast<const float4*>(&Bw[(size_t)(k0 + k) * 256 + nn0 + nn4]);
    }
    __syncthreads();
#pragma unroll
    for (int k = 0; k < 16; k++) {
      float4 b4 = *reinterpret_cast<const float4*>(&sB[k * 64 + tx * 4]);
      float a[8];
#pragma unroll
      for (int i = 0; i < 8; i++) a[i] = sA[(ty * 8 + i) * 17 + k];
#pragma unroll
      for (int i = 0; i < 8; i++) {
        acc[i][0] = fmaf(a[i], b4.x, acc[i][0]);
        acc[i][1] = fmaf(a[i], b4.y, acc[i][1]);
        acc[i][2] = fmaf(a[i], b4.z, acc[i][2]);
        acc[i][3] = fmaf(a[i], b4.w, acc[i][3]);
      }
    }
    __syncthreads();
  }

  float* pout = g_part + (size_t)ks * (BATCH * 256);
#pragma unroll
  for (int i = 0; i < 8; i++)
#pragma unroll
    for (int j = 0; j < 4; j++)
      pout[(size_t)(m0 + ty * 8 + i) * 256 + nn0 + tx * 4 + j] = acc[i][j];
}

// sum the 7 split-K partials + bias + relu
__global__ __launch_bounds__(256) void fc1_reduce_kernel(const float* __restrict__ fb1) {
  int idx = blockIdx.x * 256 + threadIdx.x;  // < 262144
  float s = fb1[idx & 255];
#pragma unroll
  for (int ks = 0; ks < 7; ks++) s += g_part[(size_t)ks * (BATCH * 256) + idx];
  g_h[idx] = fmaxf(s, 0.f);
}

// ---------------- fc2 + softmax + dist broadcast + expected value ----------
__global__ __launch_bounds__(64) void fc2_kernel(
    const float* __restrict__ w2, const float* __restrict__ b2,
    const float* __restrict__ z, int NO, float* __restrict__ out) {
  __shared__ float sh[256];
  __shared__ float red[64];
  const int n = blockIdx.x, t = threadIdx.x;
  for (int i = t; i < 256; i += 64) sh[i] = g_h[n * 256 + i];
  __syncthreads();

  float logit = -3.0e38f;
  if (t < 51) {
    float s = b2[t];
#pragma unroll 4
    for (int k = 0; k < 256; k++) s = fmaf(sh[k], __ldg(&w2[k * 51 + t]), s);
    logit = s;
  }

  red[t] = logit;
  __syncthreads();
#pragma unroll
  for (int off = 32; off > 0; off >>= 1) {
    if (t < off) red[t] = fmaxf(red[t], red[t + off]);
    __syncthreads();
  }
  float mx = red[0];
  __syncthreads();

  float e = (t < 51) ? __expf(logit - mx) : 0.f;
  red[t] = e;
  __syncthreads();
#pragma unroll
  for (int off = 32; off > 0; off >>= 1) {
    if (t < off) red[t] += red[t + off];
    __syncthreads();
  }
  float inv = 1.0f / red[0];
  __syncthreads();
  float p = e * inv;

  red[t] = (t < 51) ? p * z[t] : 0.f;
  __syncthreads();
#pragma unroll
  for (int off = 32; off > 0; off >>= 1) {
    if (t < off) red[t] += red[t + off];
    __syncthreads();
  }
  float resv = red[0];

  if (t < 51) {
    size_t dbase = (size_t)n * NO * 51 + t;
    for (int j = 0; j < NO; j++) out[dbase + (size_t)j * 51] = p;
  }
  if (t == 0) {
    float* ro = out + (size_t)gridDim.x * NO * 51;
    for (int j = 0; j < NO; j++) ro[(size_t)n * NO + j] = resv;
  }
}

// ---------------- launch ----------------------------------------------------
extern "C" void kernel_launch(void* const* d_in, const int* in_sizes, int n_in,
                              void* d_out, int out_size) {
  const float* x   = (const float*)d_in[0];
  const float* cw1 = (const float*)d_in[1];
  const float* cb1 = (const float*)d_in[2];
  const float* cw2 = (const float*)d_in[3];
  const float* cb2 = (const float*)d_in[4];
  const float* cw3 = (const float*)d_in[5];
  const float* cb3 = (const float*)d_in[6];
  const float* fw1 = (const float*)d_in[7];
  const float* fb1 = (const float*)d_in[8];
  const float* fw2 = (const float*)d_in[9];
  const float* fb2 = (const float*)d_in[10];
  const float* z   = (const float*)d_in[11];
  float* out = (float*)d_out;

  int NO = out_size / (BATCH * 52);
  if (NO < 1) NO = 6;

  const int sm1 = (28224 + 8192) * 4;
  const int sm2 = (12800 + 32768) * 4;
  const int sm3 = (4 * C3_STRIDE + 36864) * 4;   // 230528 B
  cudaFuncSetAttribute(conv1_kernel, cudaFuncAttributeMaxDynamicSharedMemorySize, sm1);
  cudaFuncSetAttribute(conv2_kernel, cudaFuncAttributeMaxDynamicSharedMemorySize, sm2);
  cudaFuncSetAttribute(conv3_kernel, cudaFuncAttributeMaxDynamicSharedMemorySize, sm3);

  transpose_w_kernel<<<144, 256>>>(cw1, cw2, cw3);
  conv1_kernel<<<BATCH, 256, sm1>>>(x, cb1);
  conv2_kernel<<<BATCH, 256, sm2>>>(cb2);
  conv3_kernel<<<BATCH / 4, 512, sm3>>>(cb3);
  fc1_kernel<<<dim3(8, 4, 7), 256>>>(fw1);
  fc1_reduce_kernel<<<1024, 256>>>(fb1);
  fc2_kernel<<<BATCH, 64>>>(fw2, fb2, z, NO, out);
}

// round 16
// speedup vs baseline: 1.1739x; 1.0008x over previous
#include <cuda_runtime.h>

#define BATCH 1024

// ---------------- scratch (static device globals: no allocation allowed) ----
__device__ __align__(16) float g_buf1[BATCH * 32 * 20 * 20];   // conv1 out
__device__ __align__(16) float g_buf2[BATCH * 64 * 9 * 9];     // conv2 out
__device__ __align__(16) float g_buf3[BATCH * 64 * 7 * 7];     // conv3 out (flattened h)
__device__ __align__(16) float g_part[7 * BATCH * 256];        // fc1 split-K partials
// transposed weights: [ic][ky][kx][oc] so consecutive oc = broadcast LDS.128
__device__ __align__(16) float g_w1t[8192];    // [4][8][8][32]
__device__ __align__(16) float g_w2t[32768];   // [32][4][4][64]
__device__ __align__(16) float g_w3t[36864];   // [64][3][3][64]

// ---------------- weight transpose (runs once per launch, ~2us) ------------
__global__ __launch_bounds__(256) void transpose_w_kernel(
    const float* __restrict__ w1, const float* __restrict__ w2,
    const float* __restrict__ w3) {
  int i = blockIdx.x * 256 + threadIdx.x;
  if (i < 8192) {            // [r=ic*ky*kx(256)][oc32] <- [oc][r]
    int oc = i & 31, r = i >> 5;
    g_w1t[i] = w1[oc * 256 + r];
  }
  if (i < 32768) {           // [r(512)][oc64]
    int oc = i & 63, r = i >> 6;
    g_w2t[i] = w2[oc * 512 + r];
  }
  if (i < 36864) {           // [r(576)][oc64]
    int oc = i & 63, r = i >> 6;
    g_w3t[i] = w3[oc * 576 + r];
  }
}

// ---------------- conv1: 4->32, 8x8 stride 4, 84->20, x scaled 1/256 -------
// R11 config (measured best): grid=B, 256 thr. lane 0..63 -> 7 px (stride 64),
// ocg 0..3 -> 8 oc. smem: 28224f + 8192f = 145664 B.
__global__ __launch_bounds__(256) void conv1_kernel(
    const float* __restrict__ x, const float* __restrict__ bias) {
  extern __shared__ float sm[];
  float* s_in = sm;
  float* s_w  = sm + 28224;
  float4* s_in4 = (float4*)s_in;
  float4* s_w4  = (float4*)s_w;
  const int n = blockIdx.x;
  const float4* xn = (const float4*)(x + (size_t)n * 28224);
  for (int i = threadIdx.x; i < 7056; i += 256) {
    float4 v = xn[i];
    v.x *= (1.0f / 256.0f); v.y *= (1.0f / 256.0f);
    v.z *= (1.0f / 256.0f); v.w *= (1.0f / 256.0f);
    s_in4[i] = v;
  }
  const float4* wt = (const float4*)g_w1t;
  for (int i = threadIdx.x; i < 2048; i += 256) s_w4[i] = wt[i];
  __syncthreads();

  const int lane = threadIdx.x & 63;
  const int ocg  = threadIdx.x >> 6;   // uniform per warp -> broadcast weight LDS

  float acc[7][8];
  int oy[7], ox[7];
#pragma unroll
  for (int pp = 0; pp < 7; pp++) {
    int p = lane + 64 * pp;
    int pq = (p < 400) ? p : 0;
    oy[pp] = pq / 20;
    ox[pp] = pq - 20 * oy[pp];
#pragma unroll
    for (int j = 0; j < 8; j++) acc[pp][j] = 0.f;
  }

#pragma unroll 1
  for (int ic = 0; ic < 4; ic++) {
#pragma unroll 1
    for (int ky = 0; ky < 8; ky++) {
      int b4[7];
#pragma unroll
      for (int pp = 0; pp < 7; pp++)
        b4[pp] = (ic * 84 + oy[pp] * 4 + ky) * 21 + ox[pp];  // float4 units
#pragma unroll
      for (int half = 0; half < 2; half++) {
        float av[7][4];
#pragma unroll
        for (int pp = 0; pp < 7; pp++) {
          float4 a = s_in4[b4[pp] + half];
          av[pp][0] = a.x; av[pp][1] = a.y; av[pp][2] = a.z; av[pp][3] = a.w;
        }
#pragma unroll
        for (int kx4 = 0; kx4 < 4; kx4++) {
          int widx = (((ic * 8 + ky) * 8 + half * 4 + kx4) * 32 + ocg * 8) >> 2;
          float4 w0 = s_w4[widx], w1 = s_w4[widx + 1];
#pragma unroll
          for (int pp = 0; pp < 7; pp++) {
            float v = av[pp][kx4];
            acc[pp][0] = fmaf(v, w0.x, acc[pp][0]);
            acc[pp][1] = fmaf(v, w0.y, acc[pp][1]);
            acc[pp][2] = fmaf(v, w0.z, acc[pp][2]);
            acc[pp][3] = fmaf(v, w0.w, acc[pp][3]);
            acc[pp][4] = fmaf(v, w1.x, acc[pp][4]);
            acc[pp][5] = fmaf(v, w1.y, acc[pp][5]);
            acc[pp][6] = fmaf(v, w1.z, acc[pp][6]);
            acc[pp][7] = fmaf(v, w1.w, acc[pp][7]);
          }
        }
      }
    }
  }

#pragma unroll
  for (int pp = 0; pp < 7; pp++) {
    int p = lane + 64 * pp;
    if (p < 400) {
#pragma unroll
      for (int j = 0; j < 8; j++) {
        int oc = ocg * 8 + j;
        g_buf1[((size_t)n * 32 + oc) * 400 + p] = fmaxf(acc[pp][j] + bias[oc], 0.f);
      }
    }
  }
}

// ---------------- conv2: 32->64, 4x4 stride 2, 20->9 -----------------------
// grid=B, 256 thr (best measured). lane 0..31 -> 3 px, ocg 0..7.
// smem: 12800f + 32768f = 182272 B.
__global__ __launch_bounds__(256) void conv2_kernel(const float* __restrict__ bias) {
  extern __shared__ float sm[];
  float* s_in = sm;           // [32][20][20]
  float* s_w  = sm + 12800;   // transposed [32][4][4][64]
  float4* s_in4 = (float4*)s_in;
  float4* s_w4  = (float4*)s_w;
  const float2* s_in2 = (const float2*)s_in;
  const int n = blockIdx.x;
  const float4* inn = (const float4*)(g_buf1 + (size_t)n * 12800);
  for (int i = threadIdx.x; i < 3200; i += 256) s_in4[i] = inn[i];
  const float4* wt = (const float4*)g_w2t;
  for (int i = threadIdx.x; i < 8192; i += 256) s_w4[i] = wt[i];
  __syncthreads();

  const int lane = threadIdx.x & 31;
  const int ocg  = threadIdx.x >> 5;

  float acc[3][8];
  int oy[3], ox[3];
#pragma unroll
  for (int pp = 0; pp < 3; pp++) {
    int p = lane + 32 * pp;
    int pq = (p < 81) ? p : 0;
    oy[pp] = pq / 9;
    ox[pp] = pq - 9 * oy[pp];
#pragma unroll
    for (int j = 0; j < 8; j++) acc[pp][j] = 0.f;
  }

#pragma unroll 1
  for (int ic = 0; ic < 32; ic++) {
#pragma unroll 1
    for (int ky = 0; ky < 4; ky++) {
      float av[3][4];
#pragma unroll
      for (int pp = 0; pp < 3; pp++) {
        int b2 = (ic * 20 + oy[pp] * 2 + ky) * 10 + ox[pp];  // float2 units
        float2 a = s_in2[b2], b = s_in2[b2 + 1];
        av[pp][0] = a.x; av[pp][1] = a.y; av[pp][2] = b.x; av[pp][3] = b.y;
      }
#pragma unroll
      for (int kx = 0; kx < 4; kx++) {
        int widx = (((ic * 4 + ky) * 4 + kx) * 64 + ocg * 8) >> 2;
        float4 w0 = s_w4[widx], w1 = s_w4[widx + 1];
#pragma unroll
        for (int pp = 0; pp < 3; pp++) {
          float v = av[pp][kx];
          acc[pp][0] = fmaf(v, w0.x, acc[pp][0]);
          acc[pp][1] = fmaf(v, w0.y, acc[pp][1]);
          acc[pp][2] = fmaf(v, w0.z, acc[pp][2]);
          acc[pp][3] = fmaf(v, w0.w, acc[pp][3]);
          acc[pp][4] = fmaf(v, w1.x, acc[pp][4]);
          acc[pp][5] = fmaf(v, w1.y, acc[pp][5]);
          acc[pp][6] = fmaf(v, w1.z, acc[pp][6]);
          acc[pp][7] = fmaf(v, w1.w, acc[pp][7]);
        }
      }
    }
  }

#pragma unroll
  for (int pp = 0; pp < 3; pp++) {
    int p = lane + 32 * pp;
    if (p < 81) {
#pragma unroll
      for (int j = 0; j < 8; j++) {
        int oc = ocg * 8 + j;
        g_buf2[((size_t)n * 64 + oc) * 81 + p] = fmaxf(acc[pp][j] + bias[oc], 0.f);
      }
    }
  }
}

// ---------------- conv3: 64->64, 3x3 stride 1, 9->7 ------------------------
// ROW-REUSE + 16 warps (measured best): thread = full 7-px row x 4 oc.
// smem: 4*5192f + 36864f = 230528 B.
#define C3_STRIDE 5192
__global__ __launch_bounds__(512) void conv3_kernel(const float* __restrict__ bias) {
  extern __shared__ float sm[];
  float* s_in = sm;                       // [4][5192]
  float* s_w  = sm + 4 * C3_STRIDE;       // transposed [64][3][3][64]
  float4* s_w4 = (float4*)s_w;
  const int n0 = blockIdx.x * 4;
#pragma unroll
  for (int img = 0; img < 4; img++) {
    const float4* src = (const float4*)(g_buf2 + (size_t)(n0 + img) * 5184);
    float4* dst = (float4*)(s_in + img * C3_STRIDE);
    for (int i = threadIdx.x; i < 1296; i += 512) dst[i] = src[i];
  }
  const float4* wt = (const float4*)g_w3t;
  for (int i = threadIdx.x; i < 9216; i += 512) s_w4[i] = wt[i];
  __syncthreads();

  const int ocg  = threadIdx.x >> 5;       // warp id 0..15 -> 4 oc (uniform)
  const int lane = threadIdx.x & 31;
  const int img  = lane / 7;               // 0..3 valid; lanes 28..31 idle
  const int row  = lane % 7;
  const bool active = (lane < 28);
  const float* s_im = s_in + (active ? img : 0) * C3_STRIDE;

  float acc[7][4];
#pragma unroll
  for (int p = 0; p < 7; p++)
#pragma unroll
    for (int j = 0; j < 4; j++) acc[p][j] = 0.f;

#pragma unroll 1
  for (int ic = 0; ic < 64; ic++) {
#pragma unroll 1
    for (int ky = 0; ky < 3; ky++) {
      const float* ip = s_im + (ic * 9 + row + ky) * 9;
      float in[9];
#pragma unroll
      for (int i = 0; i < 9; i++) in[i] = ip[i];
#pragma unroll
      for (int kx = 0; kx < 3; kx++) {
        int widx = (((ic * 3 + ky) * 3 + kx) * 64 + ocg * 4) >> 2;
        float4 w0 = s_w4[widx];
#pragma unroll
        for (int p = 0; p < 7; p++) {
          float v = in[p + kx];
          acc[p][0] = fmaf(v, w0.x, acc[p][0]);
          acc[p][1] = fmaf(v, w0.y, acc[p][1]);
          acc[p][2] = fmaf(v, w0.z, acc[p][2]);
          acc[p][3] = fmaf(v, w0.w, acc[p][3]);
        }
      }
    }
  }

  if (active) {
    const int n = n0 + img;
#pragma unroll
    for (int j = 0; j < 4; j++) {
      int oc = ocg * 4 + j;
      float b = bias[oc];
      float* dst = g_buf3 + (size_t)n * 3136 + oc * 49 + row * 7;
#pragma unroll
      for (int p = 0; p < 7; p++) dst[p] = fmaxf(acc[p][j] + b, 0.f);
    }
  }
}

// ---------------- fc1: [1024,3136] @ [3136,256], split-K=7 SGEMM -----------
// K-MAJOR sA: a-loads become 2x LDS.128 (broadcast), ratio 32 FMA : 3 LDS.128.
// grid (mt=8, nt=4, ks=7), 256 thr. tile 128x64, thread tile 8x4, kc=16.
#define SA_STRIDE 132   // 128 + 4 pad (16B-aligned rows, bank-shifted by 4)
__global__ __launch_bounds__(256) void fc1_kernel(const float* __restrict__ Bw) {
  __shared__ __align__(16) float sA[16 * SA_STRIDE];   // [k][m]
  __shared__ __align__(16) float sB[16 * 64];          // [k][n]
  const int mt = blockIdx.x, nt = blockIdx.y, ks = blockIdx.z;
  const int tid = threadIdx.x;
  const int ty = tid >> 4, tx = tid & 15;
  const int m0 = mt * 128, nn0 = nt * 64;
  const float* A = g_buf3;

  // A-load mapping: two float4 per thread; warp-uniform kq -> conflict-free STS
  const int lm  = tid & 127;        // m row
  const int kq0 = (tid >> 7) * 4;   // 0 or 4 (uniform per warp)

  float acc[8][4];
#pragma unroll
  for (int i = 0; i < 8; i++)
#pragma unroll
    for (int j = 0; j < 4; j++) acc[i][j] = 0.f;

#pragma unroll 1
  for (int kb = 0; kb < 448; kb += 16) {
    const int k0 = ks * 448 + kb;
#pragma unroll
    for (int li = 0; li < 2; li++) {
      int kq = kq0 + li * 8;        // 0/4 then 8/12
      float4 v = *reinterpret_cast<const float4*>(
          &A[(size_t)(m0 + lm) * 3136 + k0 + kq]);
      sA[(kq + 0) * SA_STRIDE + lm] = v.x;
      sA[(kq + 1) * SA_STRIDE + lm] = v.y;
      sA[(kq + 2) * SA_STRIDE + lm] = v.z;
      sA[(kq + 3) * SA_STRIDE + lm] = v.w;
    }
    {
      int k = tid >> 4;
      int nn4 = (tid & 15) << 2;
      *reinterpret_cast<float4*>(&sB[k * 64 + nn4]) =
          *reinterpret_cast<const float4*>(&Bw[(size_t)(k0 + k) * 256 + nn0 + nn4]);
    }
    __syncthreads();
#pragma unroll
    for (int k = 0; k < 16; k++) {
      float4 b4 = *reinterpret_cast<const float4*>(&sB[k * 64 + tx * 4]);
      float4 a0 = *reinterpret_cast<const float4*>(&sA[k * SA_STRIDE + ty * 8]);
      float4 a1 = *reinterpret_cast<const float4*>(&sA[k * SA_STRIDE + ty * 8 + 4]);
      float a[8] = {a0.x, a0.y, a0.z, a0.w, a1.x, a1.y, a1.z, a1.w};
#pragma unroll
      for (int i = 0; i < 8; i++) {
        acc[i][0] = fmaf(a[i], b4.x, acc[i][0]);
        acc[i][1] = fmaf(a[i], b4.y, acc[i][1]);
        acc[i][2] = fmaf(a[i], b4.z, acc[i][2]);
        acc[i][3] = fmaf(a[i], b4.w, acc[i][3]);
      }
    }
    __syncthreads();
  }

  float* pout = g_part + (size_t)ks * (BATCH * 256);
#pragma unroll
  for (int i = 0; i < 8; i++)
#pragma unroll
    for (int j = 0; j < 4; j++)
      pout[(size_t)(m0 + ty * 8 + i) * 256 + nn0 + tx * 4 + j] = acc[i][j];
}

// ---------------- fc2: fused split-K reduce + relu + fc2 + softmax + out ---
__global__ __launch_bounds__(64) void fc2_kernel(
    const float* __restrict__ fb1,
    const float* __restrict__ w2, const float* __restrict__ b2,
    const float* __restrict__ z, int NO, float* __restrict__ out) {
  __shared__ float sh[256];
  __shared__ float red[64];
  const int n = blockIdx.x, t = threadIdx.x;

  // h[t*4..t*4+3] = relu(sum_ks part + bias)
  {
    float4 s = *reinterpret_cast<const float4*>(&fb1[t * 4]);
#pragma unroll
    for (int ks = 0; ks < 7; ks++) {
      float4 p = *reinterpret_cast<const float4*>(
          &g_part[(size_t)ks * (BATCH * 256) + n * 256 + t * 4]);
      s.x += p.x; s.y += p.y; s.z += p.z; s.w += p.w;
    }
    sh[t * 4 + 0] = fmaxf(s.x, 0.f);
    sh[t * 4 + 1] = fmaxf(s.y, 0.f);
    sh[t * 4 + 2] = fmaxf(s.z, 0.f);
    sh[t * 4 + 3] = fmaxf(s.w, 0.f);
  }
  __syncthreads();

  float logit = -3.0e38f;
  if (t < 51) {
    float s = b2[t];
#pragma unroll 4
    for (int k = 0; k < 256; k++) s = fmaf(sh[k], __ldg(&w2[k * 51 + t]), s);
    logit = s;
  }

  red[t] = logit;
  __syncthreads();
#pragma unroll
  for (int off = 32; off > 0; off >>= 1) {
    if (t < off) red[t] = fmaxf(red[t], red[t + off]);
    __syncthreads();
  }
  float mx = red[0];
  __syncthreads();

  float e = (t < 51) ? __expf(logit - mx) : 0.f;
  red[t] = e;
  __syncthreads();
#pragma unroll
  for (int off = 32; off > 0; off >>= 1) {
    if (t < off) red[t] += red[t + off];
    __syncthreads();
  }
  float inv = 1.0f / red[0];
  __syncthreads();
  float p = e * inv;

  red[t] = (t < 51) ? p * z[t] : 0.f;
  __syncthreads();
#pragma unroll
  for (int off = 32; off > 0; off >>= 1) {
    if (t < off) red[t] += red[t + off];
    __syncthreads();
  }
  float resv = red[0];

  if (t < 51) {
    size_t dbase = (size_t)n * NO * 51 + t;
    for (int j = 0; j < NO; j++) out[dbase + (size_t)j * 51] = p;
  }
  if (t == 0) {
    float* ro = out + (size_t)gridDim.x * NO * 51;
    for (int j = 0; j < NO; j++) ro[(size_t)n * NO + j] = resv;
  }
}

// ---------------- launch ----------------------------------------------------
extern "C" void kernel_launch(void* const* d_in, const int* in_sizes, int n_in,
                              void* d_out, int out_size) {
  const float* x   = (const float*)d_in[0];
  const float* cw1 = (const float*)d_in[1];
  const float* cb1 = (const float*)d_in[2];
  const float* cw2 = (const float*)d_in[3];
  const float* cb2 = (const float*)d_in[4];
  const float* cw3 = (const float*)d_in[5];
  const float* cb3 = (const float*)d_in[6];
  const float* fw1 = (const float*)d_in[7];
  const float* fb1 = (const float*)d_in[8];
  const float* fw2 = (const float*)d_in[9];
  const float* fb2 = (const float*)d_in[10];
  const float* z   = (const float*)d_in[11];
  float* out = (float*)d_out;

  int NO = out_size / (BATCH * 52);
  if (NO < 1) NO = 6;

  const int sm1 = (28224 + 8192) * 4;
  const int sm2 = (12800 + 32768) * 4;
  const int sm3 = (4 * C3_STRIDE + 36864) * 4;   // 230528 B
  cudaFuncSetAttribute(conv1_kernel, cudaFuncAttributeMaxDynamicSharedMemorySize, sm1);
  cudaFuncSetAttribute(conv2_kernel, cudaFuncAttributeMaxDynamicSharedMemorySize, sm2);
  cudaFuncSetAttribute(conv3_kernel, cudaFuncAttributeMaxDynamicSharedMemorySize, sm3);

  transpose_w_kernel<<<144, 256>>>(cw1, cw2, cw3);
  conv1_kernel<<<BATCH, 256, sm1>>>(x, cb1);
  conv2_kernel<<<BATCH, 256, sm2>>>(cb2);
  conv3_kernel<<<BATCH / 4, 512, sm3>>>(cb3);
  fc1_kernel<<<dim3(8, 4, 7), 256>>>(fw1);
  fc2_kernel<<<BATCH, 64>>>(fb1, fw2, fb2, z, NO, out);
}

// round 17
// speedup vs baseline: 1.1775x; 1.0031x over previous
#include <cuda_runtime.h>

#define BATCH 1024

// ---------------- scratch (static device globals: no allocation allowed) ----
__device__ __align__(16) float g_buf1[BATCH * 32 * 20 * 20];   // conv1 out
__device__ __align__(16) float g_buf2[BATCH * 64 * 9 * 9];     // conv2 out
__device__ __align__(16) float g_buf3[BATCH * 64 * 7 * 7];     // conv3 out (flattened h)
__device__ __align__(16) float g_part[7 * BATCH * 256];        // fc1 split-K partials
// transposed weights: [ic][ky][kx][oc] so consecutive oc = broadcast LDS.128
__device__ __align__(16) float g_w1t[8192];    // [4][8][8][32]
__device__ __align__(16) float g_w2t[32768];   // [32][4][4][64]
__device__ __align__(16) float g_w3t[36864];   // [64][3][3][64]

// ---------------- weight transpose (runs once per launch, ~2us) ------------
__global__ __launch_bounds__(256) void transpose_w_kernel(
    const float* __restrict__ w1, const float* __restrict__ w2,
    const float* __restrict__ w3) {
  int i = blockIdx.x * 256 + threadIdx.x;
  if (i < 8192) {            // [r=ic*ky*kx(256)][oc32] <- [oc][r]
    int oc = i & 31, r = i >> 5;
    g_w1t[i] = w1[oc * 256 + r];
  }
  if (i < 32768) {           // [r(512)][oc64]
    int oc = i & 63, r = i >> 6;
    g_w2t[i] = w2[oc * 512 + r];
  }
  if (i < 36864) {           // [r(576)][oc64]
    int oc = i & 63, r = i >> 6;
    g_w3t[i] = w3[oc * 576 + r];
  }
}

// ---------------- conv1: 4->32, 8x8 stride 4, 84->20, x scaled 1/256 -------
// R11 config (measured best): grid=B, 256 thr. lane 0..63 -> 7 px (stride 64),
// ocg 0..3 -> 8 oc. smem: 28224f + 8192f = 145664 B.
__global__ __launch_bounds__(256) void conv1_kernel(
    const float* __restrict__ x, const float* __restrict__ bias) {
  extern __shared__ float sm[];
  float* s_in = sm;
  float* s_w  = sm + 28224;
  float4* s_in4 = (float4*)s_in;
  float4* s_w4  = (float4*)s_w;
  const int n = blockIdx.x;
  const float4* xn = (const float4*)(x + (size_t)n * 28224);
  for (int i = threadIdx.x; i < 7056; i += 256) {
    float4 v = xn[i];
    v.x *= (1.0f / 256.0f); v.y *= (1.0f / 256.0f);
    v.z *= (1.0f / 256.0f); v.w *= (1.0f / 256.0f);
    s_in4[i] = v;
  }
  const float4* wt = (const float4*)g_w1t;
  for (int i = threadIdx.x; i < 2048; i += 256) s_w4[i] = wt[i];
  __syncthreads();

  const int lane = threadIdx.x & 63;
  const int ocg  = threadIdx.x >> 6;   // uniform per warp -> broadcast weight LDS

  float acc[7][8];
  int oy[7], ox[7];
#pragma unroll
  for (int pp = 0; pp < 7; pp++) {
    int p = lane + 64 * pp;
    int pq = (p < 400) ? p : 0;
    oy[pp] = pq / 20;
    ox[pp] = pq - 20 * oy[pp];
#pragma unroll
    for (int j = 0; j < 8; j++) acc[pp][j] = 0.f;
  }

#pragma unroll 1
  for (int ic = 0; ic < 4; ic++) {
#pragma unroll 1
    for (int ky = 0; ky < 8; ky++) {
      int b4[7];
#pragma unroll
      for (int pp = 0; pp < 7; pp++)
        b4[pp] = (ic * 84 + oy[pp] * 4 + ky) * 21 + ox[pp];  // float4 units
#pragma unroll
      for (int half = 0; half < 2; half++) {
        float av[7][4];
#pragma unroll
        for (int pp = 0; pp < 7; pp++) {
          float4 a = s_in4[b4[pp] + half];
          av[pp][0] = a.x; av[pp][1] = a.y; av[pp][2] = a.z; av[pp][3] = a.w;
        }
#pragma unroll
        for (int kx4 = 0; kx4 < 4; kx4++) {
          int widx = (((ic * 8 + ky) * 8 + half * 4 + kx4) * 32 + ocg * 8) >> 2;
          float4 w0 = s_w4[widx], w1 = s_w4[widx + 1];
#pragma unroll
          for (int pp = 0; pp < 7; pp++) {
            float v = av[pp][kx4];
            acc[pp][0] = fmaf(v, w0.x, acc[pp][0]);
            acc[pp][1] = fmaf(v, w0.y, acc[pp][1]);
            acc[pp][2] = fmaf(v, w0.z, acc[pp][2]);
            acc[pp][3] = fmaf(v, w0.w, acc[pp][3]);
            acc[pp][4] = fmaf(v, w1.x, acc[pp][4]);
            acc[pp][5] = fmaf(v, w1.y, acc[pp][5]);
            acc[pp][6] = fmaf(v, w1.z, acc[pp][6]);
            acc[pp][7] = fmaf(v, w1.w, acc[pp][7]);
          }
        }
      }
    }
  }

#pragma unroll
  for (int pp = 0; pp < 7; pp++) {
    int p = lane + 64 * pp;
    if (p < 400) {
#pragma unroll
      for (int j = 0; j < 8; j++) {
        int oc = ocg * 8 + j;
        g_buf1[((size_t)n * 32 + oc) * 400 + p] = fmaxf(acc[pp][j] + bias[oc], 0.f);
      }
    }
  }
}

// ---------------- conv2: 32->64, 4x4 stride 2, 20->9 -----------------------
// grid=B, 256 thr (best measured). lane 0..31 -> 3 px, ocg 0..7.
// smem: 12800f + 32768f = 182272 B.
__global__ __launch_bounds__(256) void conv2_kernel(const float* __restrict__ bias) {
  extern __shared__ float sm[];
  float* s_in = sm;           // [32][20][20]
  float* s_w  = sm + 12800;   // transposed [32][4][4][64]
  float4* s_in4 = (float4*)s_in;
  float4* s_w4  = (float4*)s_w;
  const float2* s_in2 = (const float2*)s_in;
  const int n = blockIdx.x;
  const float4* inn = (const float4*)(g_buf1 + (size_t)n * 12800);
  for (int i = threadIdx.x; i < 3200; i += 256) s_in4[i] = inn[i];
  const float4* wt = (const float4*)g_w2t;
  for (int i = threadIdx.x; i < 8192; i += 256) s_w4[i] = wt[i];
  __syncthreads();

  const int lane = threadIdx.x & 31;
  const int ocg  = threadIdx.x >> 5;

  float acc[3][8];
  int oy[3], ox[3];
#pragma unroll
  for (int pp = 0; pp < 3; pp++) {
    int p = lane + 32 * pp;
    int pq = (p < 81) ? p : 0;
    oy[pp] = pq / 9;
    ox[pp] = pq - 9 * oy[pp];
#pragma unroll
    for (int j = 0; j < 8; j++) acc[pp][j] = 0.f;
  }

#pragma unroll 1
  for (int ic = 0; ic < 32; ic++) {
#pragma unroll 1
    for (int ky = 0; ky < 4; ky++) {
      float av[3][4];
#pragma unroll
      for (int pp = 0; pp < 3; pp++) {
        int b2 = (ic * 20 + oy[pp] * 2 + ky) * 10 + ox[pp];  // float2 units
        float2 a = s_in2[b2], b = s_in2[b2 + 1];
        av[pp][0] = a.x; av[pp][1] = a.y; av[pp][2] = b.x; av[pp][3] = b.y;
      }
#pragma unroll
      for (int kx = 0; kx < 4; kx++) {
        int widx = (((ic * 4 + ky) * 4 + kx) * 64 + ocg * 8) >> 2;
        float4 w0 = s_w4[widx], w1 = s_w4[widx + 1];
#pragma unroll
        for (int pp = 0; pp < 3; pp++) {
          float v = av[pp][kx];
          acc[pp][0] = fmaf(v, w0.x, acc[pp][0]);
          acc[pp][1] = fmaf(v, w0.y, acc[pp][1]);
          acc[pp][2] = fmaf(v, w0.z, acc[pp][2]);
          acc[pp][3] = fmaf(v, w0.w, acc[pp][3]);
          acc[pp][4] = fmaf(v, w1.x, acc[pp][4]);
          acc[pp][5] = fmaf(v, w1.y, acc[pp][5]);
          acc[pp][6] = fmaf(v, w1.z, acc[pp][6]);
          acc[pp][7] = fmaf(v, w1.w, acc[pp][7]);
        }
      }
    }
  }

#pragma unroll
  for (int pp = 0; pp < 3; pp++) {
    int p = lane + 32 * pp;
    if (p < 81) {
#pragma unroll
      for (int j = 0; j < 8; j++) {
        int oc = ocg * 8 + j;
        g_buf2[((size_t)n * 64 + oc) * 81 + p] = fmaxf(acc[pp][j] + bias[oc], 0.f);
      }
    }
  }
}

// ---------------- conv3: 64->64, 3x3 stride 1, 9->7 ------------------------
// ROW-REUSE + 16 warps (measured best): thread = full 7-px row x 4 oc.
// smem: 4*5192f + 36864f = 230528 B.
#define C3_STRIDE 5192
__global__ __launch_bounds__(512) void conv3_kernel(const float* __restrict__ bias) {
  extern __shared__ float sm[];
  float* s_in = sm;                       // [4][5192]
  float* s_w  = sm + 4 * C3_STRIDE;       // transposed [64][3][3][64]
  float4* s_w4 = (float4*)s_w;
  const int n0 = blockIdx.x * 4;
#pragma unroll
  for (int img = 0; img < 4; img++) {
    const float4* src = (const float4*)(g_buf2 + (size_t)(n0 + img) * 5184);
    float4* dst = (float4*)(s_in + img * C3_STRIDE);
    for (int i = threadIdx.x; i < 1296; i += 512) dst[i] = src[i];
  }
  const float4* wt = (const float4*)g_w3t;
  for (int i = threadIdx.x; i < 9216; i += 512) s_w4[i] = wt[i];
  __syncthreads();

  const int ocg  = threadIdx.x >> 5;       // warp id 0..15 -> 4 oc (uniform)
  const int lane = threadIdx.x & 31;
  const int img  = lane / 7;               // 0..3 valid; lanes 28..31 idle
  const int row  = lane % 7;
  const bool active = (lane < 28);
  const float* s_im = s_in + (active ? img : 0) * C3_STRIDE;

  float acc[7][4];
#pragma unroll
  for (int p = 0; p < 7; p++)
#pragma unroll
    for (int j = 0; j < 4; j++) acc[p][j] = 0.f;

#pragma unroll 1
  for (int ic = 0; ic < 64; ic++) {
#pragma unroll 1
    for (int ky = 0; ky < 3; ky++) {
      const float* ip = s_im + (ic * 9 + row + ky) * 9;
      float in[9];
#pragma unroll
      for (int i = 0; i < 9; i++) in[i] = ip[i];
#pragma unroll
      for (int kx = 0; kx < 3; kx++) {
        int widx = (((ic * 3 + ky) * 3 + kx) * 64 + ocg * 4) >> 2;
        float4 w0 = s_w4[widx];
#pragma unroll
        for (int p = 0; p < 7; p++) {
          float v = in[p + kx];
          acc[p][0] = fmaf(v, w0.x, acc[p][0]);
          acc[p][1] = fmaf(v, w0.y, acc[p][1]);
          acc[p][2] = fmaf(v, w0.z, acc[p][2]);
          acc[p][3] = fmaf(v, w0.w, acc[p][3]);
        }
      }
    }
  }

  if (active) {
    const int n = n0 + img;
#pragma unroll
    for (int j = 0; j < 4; j++) {
      int oc = ocg * 4 + j;
      float b = bias[oc];
      float* dst = g_buf3 + (size_t)n * 3136 + oc * 49 + row * 7;
#pragma unroll
      for (int p = 0; p < 7; p++) dst[p] = fmaxf(acc[p][j] + b, 0.f);
    }
  }
}

// ---------------- fc1: [1024,3136] @ [3136,256], split-K=7 SGEMM -----------
// R15 version (measured best: coalesced A loads, m-major sA).
// grid (mt=8, nt=4, ks=7), 256 thr. tile 128x64, thread tile 8x4, kc=16.
__global__ __launch_bounds__(256) void fc1_kernel(const float* __restrict__ Bw) {
  __shared__ __align__(16) float sA[128 * 17];
  __shared__ __align__(16) float sB[16 * 64];
  const int mt = blockIdx.x, nt = blockIdx.y, ks = blockIdx.z;
  const int tid = threadIdx.x;
  const int ty = tid >> 4, tx = tid & 15;
  const int m0 = mt * 128, nn0 = nt * 64;
  const float* A = g_buf3;

  float acc[8][4];
#pragma unroll
  for (int i = 0; i < 8; i++)
#pragma unroll
    for (int j = 0; j < 4; j++) acc[i][j] = 0.f;

#pragma unroll 1
  for (int kb = 0; kb < 448; kb += 16) {
    const int k0 = ks * 448 + kb;
#pragma unroll
    for (int li = 0; li < 2; li++) {
      int f = tid + li * 256;          // 0..511
      int m = f >> 2;
      int kk = (f & 3) << 2;
      float4 v = *reinterpret_cast<const float4*>(
          &A[(size_t)(m0 + m) * 3136 + k0 + kk]);
      sA[m * 17 + kk + 0] = v.x;
      sA[m * 17 + kk + 1] = v.y;
      sA[m * 17 + kk + 2] = v.z;
      sA[m * 17 + kk + 3] = v.w;
    }
    {
      int k = tid >> 4;
      int nn4 = (tid & 15) << 2;
      *reinterpret_cast<float4*>(&sB[k * 64 + nn4]) =
          *reinterpret_cast<const float4*>(&Bw[(size_t)(k0 + k) * 256 + nn0 + nn4]);
    }
    __syncthreads();
#pragma unroll
    for (int k = 0; k < 16; k++) {
      float4 b4 = *reinterpret_cast<const float4*>(&sB[k * 64 + tx * 4]);
      float a[8];
#pragma unroll
      for (int i = 0; i < 8; i++) a[i] = sA[(ty * 8 + i) * 17 + k];
#pragma unroll
      for (int i = 0; i < 8; i++) {
        acc[i][0] = fmaf(a[i], b4.x, acc[i][0]);
        acc[i][1] = fmaf(a[i], b4.y, acc[i][1]);
        acc[i][2] = fmaf(a[i], b4.z, acc[i][2]);
        acc[i][3] = fmaf(a[i], b4.w, acc[i][3]);
      }
    }
    __syncthreads();
  }

  float* pout = g_part + (size_t)ks * (BATCH * 256);
#pragma unroll
  for (int i = 0; i < 8; i++)
#pragma unroll
    for (int j = 0; j < 4; j++)
      pout[(size_t)(m0 + ty * 8 + i) * 256 + nn0 + tx * 4 + j] = acc[i][j];
}

// ---------------- fc2: fused split-K reduce + relu + fc2 + softmax + out ---
__global__ __launch_bounds__(64) void fc2_kernel(
    const float* __restrict__ fb1,
    const float* __restrict__ w2, const float* __restrict__ b2,
    const float* __restrict__ z, int NO, float* __restrict__ out) {
  __shared__ float sh[256];
  __shared__ float red[64];
  const int n = blockIdx.x, t = threadIdx.x;

  // h[t*4..t*4+3] = relu(sum_ks part + bias)
  {
    float4 s = *reinterpret_cast<const float4*>(&fb1[t * 4]);
#pragma unroll
    for (int ks = 0; ks < 7; ks++) {
      float4 p = *reinterpret_cast<const float4*>(
          &g_part[(size_t)ks * (BATCH * 256) + n * 256 + t * 4]);
      s.x += p.x; s.y += p.y; s.z += p.z; s.w += p.w;
    }
    sh[t * 4 + 0] = fmaxf(s.x, 0.f);
    sh[t * 4 + 1] = fmaxf(s.y, 0.f);
    sh[t * 4 + 2] = fmaxf(s.z, 0.f);
    sh[t * 4 + 3] = fmaxf(s.w, 0.f);
  }
  __syncthreads();

  float logit = -3.0e38f;
  if (t < 51) {
    float s = b2[t];
#pragma unroll 4
    for (int k = 0; k < 256; k++) s = fmaf(sh[k], __ldg(&w2[k * 51 + t]), s);
    logit = s;
  }

  red[t] = logit;
  __syncthreads();
#pragma unroll
  for (int off = 32; off > 0; off >>= 1) {
    if (t < off) red[t] = fmaxf(red[t], red[t + off]);
    __syncthreads();
  }
  float mx = red[0];
  __syncthreads();

  float e = (t < 51) ? __expf(logit - mx) : 0.f;
  red[t] = e;
  __syncthreads();
#pragma unroll
  for (int off = 32; off > 0; off >>= 1) {
    if (t < off) red[t] += red[t + off];
    __syncthreads();
  }
  float inv = 1.0f / red[0];
  __syncthreads();
  float p = e * inv;

  red[t] = (t < 51) ? p * z[t] : 0.f;
  __syncthreads();
#pragma unroll
  for (int off = 32; off > 0; off >>= 1) {
    if (t < off) red[t] += red[t + off];
    __syncthreads();
  }
  float resv = red[0];

  if (t < 51) {
    size_t dbase = (size_t)n * NO * 51 + t;
    for (int j = 0; j < NO; j++) out[dbase + (size_t)j * 51] = p;
  }
  if (t == 0) {
    float* ro = out + (size_t)gridDim.x * NO * 51;
    for (int j = 0; j < NO; j++) ro[(size_t)n * NO + j] = resv;
  }
}

// ---------------- launch ----------------------------------------------------
extern "C" void kernel_launch(void* const* d_in, const int* in_sizes, int n_in,
                              void* d_out, int out_size) {
  const float* x   = (const float*)d_in[0];
  const float* cw1 = (const float*)d_in[1];
  const float* cb1 = (const float*)d_in[2];
  const float* cw2 = (const float*)d_in[3];
  const float* cb2 = (const float*)d_in[4];
  const float* cw3 = (const float*)d_in[5];
  const float* cb3 = (const float*)d_in[6];
  const float* fw1 = (const float*)d_in[7];
  const float* fb1 = (const float*)d_in[8];
  const float* fw2 = (const float*)d_in[9];
  const float* fb2 = (const float*)d_in[10];
  const float* z   = (const float*)d_in[11];
  float* out = (float*)d_out;

  int NO = out_size / (BATCH * 52);
  if (NO < 1) NO = 6;

  const int sm1 = (28224 + 8192) * 4;
  const int sm2 = (12800 + 32768) * 4;
  const int sm3 = (4 * C3_STRIDE + 36864) * 4;   // 230528 B
  cudaFuncSetAttribute(conv1_kernel, cudaFuncAttributeMaxDynamicSharedMemorySize, sm1);
  cudaFuncSetAttribute(conv2_kernel, cudaFuncAttributeMaxDynamicSharedMemorySize, sm2);
  cudaFuncSetAttribute(conv3_kernel, cudaFuncAttributeMaxDynamicSharedMemorySize, sm3);

  transpose_w_kernel<<<144, 256>>>(cw1, cw2, cw3);
  conv1_kernel<<<BATCH, 256, sm1>>>(x, cb1);
  conv2_kernel<<<BATCH, 256, sm2>>>(cb2);
  conv3_kernel<<<BATCH / 4, 512, sm3>>>(cb3);
  fc1_kernel<<<dim3(8, 4, 7), 256>>>(fw1);
  fc2_kernel<<<BATCH, 64>>>(fb1, fw2, fb2, z, NO, out);
}